// round 6
// baseline (speedup 1.0000x reference)
#include <cuda_runtime.h>
#include <cstdint>

#define T_ 12
#define N_ 10000
#define F_ 128
#define H_ 128
#define E_ 320000
#define NH (N_*H_)
#define TNH (T_*NH)
#define WSLICE (3*F_*H_)        // 49152 floats per gate weight tensor

// ---------------- scratch (static device memory; zero-initialized at load) ----------------
__device__ __align__(16) float g_TxB1[TNH];   // batched x-chain hop1, all steps
__device__ __align__(16) float g_TxB2[TNH];   // batched x-chain hop2
__device__ __align__(16) float g_XZ [TNH];    // precomputed x-side gate pre-activations
__device__ __align__(16) float g_XR [TNH];
__device__ __align__(16) float g_XH [TNH];
__device__ __align__(16) float g_Th1[NH];
__device__ __align__(16) float g_Th2[NH];
__device__ __align__(16) float g_Ts1[NH];
__device__ __align__(16) float g_Ts2[NH];
__device__ __align__(16) float g_h  [NH];     // zero-init; re-zeroed by final k_proj
__device__ __align__(16) float g_z  [NH];
__device__ __align__(16) float g_s  [NH];
__device__ __align__(16) float g_W  [6 * WSLICE];   // tf32-rounded weights
__device__ float g_deg[N_];       // zero-init; re-zeroed by batched hop1 prop
__device__ int   g_cnt[N_];       // zero-init; re-zeroed by batched hop1 prop
__device__ int   g_rowptr[N_ + 1];
__device__ int   g_wr[N_];        // write cursors for CSR fill
__device__ int   g_col[E_];
__device__ float g_val[E_];

// per-thread edge dtype probe: int64 values < 2^32 -> odd int32 words all zero
__device__ __forceinline__ bool probe_is64(const void* ei) {
    const int* p = (const int*)ei;
    int acc = 0;
#pragma unroll
    for (int i = 1; i < 32; i += 2) acc |= p[i];
    return acc == 0;
}
__device__ __forceinline__ int edge_at(const void* ei, int idx, bool is64) {
    if (is64) return (int)((const long long*)ei)[idx];
    return ((const int*)ei)[idx];
}

// ---------------- preprocessing (3 launches) ----------------
// counts + degree + weight tf32 pre-rounding
struct W6 { const float* p[6]; };
__global__ void k_count(const void* __restrict__ ei, W6 w) {
    int e = blockIdx.x * blockDim.x + threadIdx.x;
    if (e < 6 * WSLICE) {
        int which = e / WSLICE;
        int off = e - which * WSLICE;
        float v = w.p[which][off];
        uint32_t r;
        asm("cvt.rna.tf32.f32 %0, %1;" : "=r"(r) : "f"(v));
        g_W[e] = __uint_as_float(r);
    }
    if (e >= E_) return;
    bool is64 = probe_is64(ei);
    int s = edge_at(ei, e, is64);
    int d = edge_at(ei, E_ + e, is64);
    if ((unsigned)s >= N_ || (unsigned)d >= N_) return;
    atomicAdd(&g_deg[s], 1.0f);
    atomicAdd(&g_cnt[d], 1);
}

// dinv + exclusive prefix sum + write-cursor init (single block, 1024 threads)
__global__ void k_scan() {
    __shared__ int sh[1024];
    int tid = threadIdx.x;
    for (int i = tid; i < N_; i += 1024) {
        float d = g_deg[i];
        g_deg[i] = (d > 0.f) ? rsqrtf(d) : 0.f;
    }
    const int PER = (N_ + 1023) / 1024;
    int base = tid * PER;
    int s = 0;
    for (int i = 0; i < PER; i++) { int ix = base + i; if (ix < N_) s += g_cnt[ix]; }
    sh[tid] = s;
    __syncthreads();
    for (int off = 1; off < 1024; off <<= 1) {
        int v = (tid >= off) ? sh[tid - off] : 0;
        __syncthreads();
        if (tid >= off) sh[tid] += v;
        __syncthreads();
    }
    int run = (tid > 0) ? sh[tid - 1] : 0;
    for (int i = 0; i < PER; i++) {
        int ix = base + i;
        if (ix < N_) { g_rowptr[ix] = run; g_wr[ix] = run; run += g_cnt[ix]; }
    }
    if (tid == 0) g_rowptr[N_] = sh[1023];
}

__global__ void k_fill(const void* __restrict__ ei) {
    int e = blockIdx.x * blockDim.x + threadIdx.x;
    if (e >= E_) return;
    bool is64 = probe_is64(ei);
    int s = edge_at(ei, e, is64);
    int d = edge_at(ei, E_ + e, is64);
    if ((unsigned)s >= N_ || (unsigned)d >= N_) return;
    int slot = atomicAdd(&g_wr[d], 1);
    g_col[slot] = s;
    g_val[slot] = -g_deg[s] * g_deg[d];
}

// ---------------- graph propagation (optionally batched over steps) ----------------
// out[t,n,:] = scale * sum_e val*in[t,col,:] - sub[t,n,:]
// grid (N_, n_steps); clear=1 additionally re-zeroes g_cnt/g_deg for next replay.
__global__ void k_propb(const float* __restrict__ in, float* __restrict__ out,
                        const float* __restrict__ sub, float scale, int clear) {
    int n = blockIdx.x;
    int t = blockIdx.y;
    int j = threadIdx.x;
    if (clear && t == 0 && j == 0) { g_cnt[n] = 0; g_deg[n] = 0.f; }
    size_t off = (size_t)t * NH;
    in += off; out += off; if (sub) sub += off;
    int e = g_rowptr[n], end = g_rowptr[n + 1];
    float a0 = 0.f, a1 = 0.f, a2 = 0.f, a3 = 0.f;
    for (; e + 4 <= end; e += 4) {
        int   c0 = g_col[e],     c1 = g_col[e + 1], c2 = g_col[e + 2], c3 = g_col[e + 3];
        float w0 = g_val[e],     w1 = g_val[e + 1], w2 = g_val[e + 2], w3 = g_val[e + 3];
        a0 += w0 * __ldg(in + c0 * H_ + j);
        a1 += w1 * __ldg(in + c1 * H_ + j);
        a2 += w2 * __ldg(in + c2 * H_ + j);
        a3 += w3 * __ldg(in + c3 * H_ + j);
    }
    float acc = (a0 + a1) + (a2 + a3);
    for (; e < end; e++) acc += g_val[e] * __ldg(in + g_col[e] * H_ + j);
    float r = scale * acc;
    if (sub) r -= sub[n * H_ + j];
    out[n * H_ + j] = r;
}

// ---------------- tf32 tensor-core GEMMs ----------------
__device__ __forceinline__ float sigf(float x) { return 1.f / (1.f + expf(-x)); }
__device__ __forceinline__ void cp16(uint32_t dst, const void* src) {
    asm volatile("cp.async.cg.shared.global [%0], [%1], 16;\n" :: "r"(dst), "l"(src));
}
__device__ __forceinline__ uint32_t f2tf32(float v) {
    uint32_t r;
    asm("cvt.rna.tf32.f32 %0, %1;" : "=r"(r) : "f"(v));
    return r;
}
__device__ __forceinline__ void mma_tf32(float c[4], const uint32_t a[4], const uint32_t b[2]) {
    asm volatile(
        "mma.sync.aligned.m16n8k8.row.col.f32.tf32.tf32.f32 "
        "{%0,%1,%2,%3}, {%4,%5,%6,%7}, {%8,%9}, {%0,%1,%2,%3};\n"
        : "+f"(c[0]), "+f"(c[1]), "+f"(c[2]), "+f"(c[3])
        : "r"(a[0]), "r"(a[1]), "r"(a[2]), "r"(a[3]), "r"(b[0]), "r"(b[1]));
}

#define AS_STRIDE 36
#define BS_STRIDE 72
#define AS_WORDS (64 * AS_STRIDE)   // 2304
#define BS_WORDS (32 * BS_STRIDE)   // 2304

// ---- batched x-side GEMM: for gate=blockIdx.z, out = sum_{p<3} A_p @ B[gate][p] + bias[gate]
struct GX {
    const float* A[3];          // x_seq, TxB1, TxB2 (120000 rows each)
    const float* B[3][3];
    const float* bias[3];
    float* out[3];
    int M;
};

__global__ __launch_bounds__(128) void k_gemm_x(GX P) {
    __shared__ float As[2][AS_WORDS];
    __shared__ float Bs[2][BS_WORDS];
    const int gate = blockIdx.z;
    const int tid  = threadIdx.x;
    const int wid  = tid >> 5, lane = tid & 31;
    const int g    = lane >> 2, tig = lane & 3;
    const int wm   = wid >> 1, wn = wid & 1;
    const int bm   = blockIdx.x * 64;
    const int bn   = blockIdx.y * 64;

    float c[2][4][4];
#pragma unroll
    for (int im = 0; im < 2; im++)
#pragma unroll
        for (int it = 0; it < 4; it++)
#pragma unroll
            for (int q = 0; q < 4; q++) c[im][it][q] = 0.f;

    auto issue = [&](int s) {
        int pr = s >> 2, ch = s & 3, buf = s & 1;
        uint32_t sA = (uint32_t)__cvta_generic_to_shared(&As[buf][0]);
        uint32_t sB = (uint32_t)__cvta_generic_to_shared(&Bs[buf][0]);
        const float* Ap = P.A[pr];
        const float* Bp = P.B[gate][pr];
#pragma unroll
        for (int i = 0; i < 4; i++) {
            int fi = tid + 128 * i;
            int row = fi >> 3, c4 = fi & 7;
            int ar = bm + row; if (ar > P.M - 1) ar = P.M - 1;
            cp16(sA + (uint32_t)(row * AS_STRIDE + c4 * 4) * 4,
                 Ap + (size_t)ar * F_ + ch * 32 + c4 * 4);
        }
#pragma unroll
        for (int i = 0; i < 4; i++) {
            int fi = tid + 128 * i;
            int row = fi >> 4, c4 = fi & 15;
            cp16(sB + (uint32_t)(row * BS_STRIDE + c4 * 4) * 4,
                 Bp + (ch * 32 + row) * H_ + bn + c4 * 4);
        }
        asm volatile("cp.async.commit_group;\n" ::: "memory");
    };

    issue(0);
#pragma unroll 1
    for (int s = 0; s < 12; s++) {          // 3 pairs x 4 k-chunks
        if (s + 1 < 12) {
            issue(s + 1);
            asm volatile("cp.async.wait_group 1;\n" ::: "memory");
        } else {
            asm volatile("cp.async.wait_group 0;\n" ::: "memory");
        }
        __syncthreads();
        const float* As_ = As[s & 1];
        const float* Bs_ = Bs[s & 1];
#pragma unroll
        for (int ks = 0; ks < 4; ks++) {
            const int k = ks * 8;
            uint32_t a[2][4];
#pragma unroll
            for (int im = 0; im < 2; im++) {
                int r0 = wm * 32 + im * 16 + g;
                a[im][0] = f2tf32(As_[r0 * AS_STRIDE + k + tig]);
                a[im][1] = f2tf32(As_[(r0 + 8) * AS_STRIDE + k + tig]);
                a[im][2] = f2tf32(As_[r0 * AS_STRIDE + k + tig + 4]);
                a[im][3] = f2tf32(As_[(r0 + 8) * AS_STRIDE + k + tig + 4]);
            }
            uint32_t b[4][2];
#pragma unroll
            for (int it = 0; it < 4; it++) {
                int cb = wn * 32 + it * 8 + g;
                b[it][0] = __float_as_uint(Bs_[(k + tig) * BS_STRIDE + cb]);
                b[it][1] = __float_as_uint(Bs_[(k + tig + 4) * BS_STRIDE + cb]);
            }
#pragma unroll
            for (int im = 0; im < 2; im++)
#pragma unroll
                for (int it = 0; it < 4; it++) mma_tf32(c[im][it], a[im], b[it]);
        }
        __syncthreads();
    }

    float* outp = P.out[gate];
    const float* bp = P.bias[gate];
#pragma unroll
    for (int im = 0; im < 2; im++) {
        int rbase = bm + wm * 32 + im * 16 + g;
#pragma unroll
        for (int half = 0; half < 2; half++) {
            int row = rbase + half * 8;
            if (row >= P.M) continue;
#pragma unroll
            for (int it = 0; it < 4; it++) {
#pragma unroll
                for (int q = 0; q < 2; q++) {
                    int col = bn + wn * 32 + it * 8 + 2 * tig + q;
                    outp[(size_t)row * H_ + col] = c[im][it][half * 2 + q] + __ldg(bp + col);
                }
            }
        }
    }
}

// ---- per-step fused z+r GEMM over h-chain, x-side added in epilogue ----
struct GZR {
    const float* A[3];          // h, Th1, Th2
    const float* Bz[3];
    const float* Br[3];
    const float* bz;            // bhz
    const float* br;            // bhr
    const float* xz;            // XZ + t*NH
    const float* xr;            // XR + t*NH
    const float* h;
    float* zout; float* sout;
};

__global__ __launch_bounds__(128) void k_gemm_zr(GZR P) {
    extern __shared__ float sm[];
    float* As = sm;
    float* Bz = sm + 2 * AS_WORDS;
    float* Br = sm + 2 * AS_WORDS + 2 * BS_WORDS;

    const int tid  = threadIdx.x;
    const int wid  = tid >> 5, lane = tid & 31;
    const int g    = lane >> 2, tig = lane & 3;
    const int wm   = wid >> 1, wn = wid & 1;
    const int bm   = blockIdx.x * 64;
    const int bn   = blockIdx.y * 64;

    float cz[2][4][4], cr[2][4][4];
#pragma unroll
    for (int im = 0; im < 2; im++)
#pragma unroll
        for (int it = 0; it < 4; it++)
#pragma unroll
            for (int q = 0; q < 4; q++) { cz[im][it][q] = 0.f; cr[im][it][q] = 0.f; }

    auto issue = [&](int s) {
        int pr = s >> 2, ch = s & 3, buf = s & 1;
        uint32_t sA = (uint32_t)__cvta_generic_to_shared(As + buf * AS_WORDS);
        uint32_t sZ = (uint32_t)__cvta_generic_to_shared(Bz + buf * BS_WORDS);
        uint32_t sR = (uint32_t)__cvta_generic_to_shared(Br + buf * BS_WORDS);
        const float* Ap = P.A[pr];
        const float* Zp = P.Bz[pr];
        const float* Rp = P.Br[pr];
#pragma unroll
        for (int i = 0; i < 4; i++) {
            int fi = tid + 128 * i;
            int row = fi >> 3, c4 = fi & 7;
            int ar = bm + row; if (ar > N_ - 1) ar = N_ - 1;
            cp16(sA + (uint32_t)(row * AS_STRIDE + c4 * 4) * 4,
                 Ap + ar * F_ + ch * 32 + c4 * 4);
        }
#pragma unroll
        for (int i = 0; i < 4; i++) {
            int fi = tid + 128 * i;
            int row = fi >> 4, c4 = fi & 15;
            cp16(sZ + (uint32_t)(row * BS_STRIDE + c4 * 4) * 4,
                 Zp + (ch * 32 + row) * H_ + bn + c4 * 4);
        }
#pragma unroll
        for (int i = 0; i < 4; i++) {
            int fi = tid + 128 * i;
            int row = fi >> 4, c4 = fi & 15;
            cp16(sR + (uint32_t)(row * BS_STRIDE + c4 * 4) * 4,
                 Rp + (ch * 32 + row) * H_ + bn + c4 * 4);
        }
        asm volatile("cp.async.commit_group;\n" ::: "memory");
    };

    issue(0);
#pragma unroll 1
    for (int s = 0; s < 12; s++) {
        if (s + 1 < 12) {
            issue(s + 1);
            asm volatile("cp.async.wait_group 1;\n" ::: "memory");
        } else {
            asm volatile("cp.async.wait_group 0;\n" ::: "memory");
        }
        __syncthreads();
        const float* As_ = As + (s & 1) * AS_WORDS;
        const float* Bz_ = Bz + (s & 1) * BS_WORDS;
        const float* Br_ = Br + (s & 1) * BS_WORDS;
#pragma unroll
        for (int ks = 0; ks < 4; ks++) {
            const int k = ks * 8;
            uint32_t a[2][4];
#pragma unroll
            for (int im = 0; im < 2; im++) {
                int r0 = wm * 32 + im * 16 + g;
                a[im][0] = f2tf32(As_[r0 * AS_STRIDE + k + tig]);
                a[im][1] = f2tf32(As_[(r0 + 8) * AS_STRIDE + k + tig]);
                a[im][2] = f2tf32(As_[r0 * AS_STRIDE + k + tig + 4]);
                a[im][3] = f2tf32(As_[(r0 + 8) * AS_STRIDE + k + tig + 4]);
            }
            uint32_t bz[4][2], br[4][2];
#pragma unroll
            for (int it = 0; it < 4; it++) {
                int cb = wn * 32 + it * 8 + g;
                bz[it][0] = __float_as_uint(Bz_[(k + tig) * BS_STRIDE + cb]);
                bz[it][1] = __float_as_uint(Bz_[(k + tig + 4) * BS_STRIDE + cb]);
                br[it][0] = __float_as_uint(Br_[(k + tig) * BS_STRIDE + cb]);
                br[it][1] = __float_as_uint(Br_[(k + tig + 4) * BS_STRIDE + cb]);
            }
#pragma unroll
            for (int im = 0; im < 2; im++)
#pragma unroll
                for (int it = 0; it < 4; it++) {
                    mma_tf32(cz[im][it], a[im], bz[it]);
                    mma_tf32(cr[im][it], a[im], br[it]);
                }
        }
        __syncthreads();
    }

#pragma unroll
    for (int im = 0; im < 2; im++) {
        int rbase = bm + wm * 32 + im * 16 + g;
#pragma unroll
        for (int half = 0; half < 2; half++) {
            int row = rbase + half * 8;
            if (row >= N_) continue;
#pragma unroll
            for (int it = 0; it < 4; it++) {
#pragma unroll
                for (int q = 0; q < 2; q++) {
                    int col = bn + wn * 32 + it * 8 + 2 * tig + q;
                    int idx = row * H_ + col;
                    float vz = cz[im][it][half * 2 + q] + __ldg(P.bz + col) + P.xz[idx];
                    float vr = cr[im][it][half * 2 + q] + __ldg(P.br + col) + P.xr[idx];
                    P.zout[idx] = sigf(vz);
                    P.sout[idx] = P.h[idx] * sigf(vr);
                }
            }
        }
    }
}

// ---- per-step h-update GEMM over s-chain: h = z*h + (1-z)*tanh(acc + bhh + XH) ----
struct GH {
    const float* A[3];          // s, Ts1, Ts2
    const float* B[3];
    const float* b;             // bhh
    const float* xh;            // XH + t*NH
    const float* h;  const float* z;
    float* out;
};

__global__ __launch_bounds__(128) void k_gemm_h(GH P) {
    __shared__ float As[2][AS_WORDS];
    __shared__ float Bs[2][BS_WORDS];

    const int tid  = threadIdx.x;
    const int wid  = tid >> 5, lane = tid & 31;
    const int g    = lane >> 2, tig = lane & 3;
    const int wm   = wid >> 1, wn = wid & 1;
    const int bm   = blockIdx.x * 64;
    const int bn   = blockIdx.y * 64;

    float c[2][4][4];
#pragma unroll
    for (int im = 0; im < 2; im++)
#pragma unroll
        for (int it = 0; it < 4; it++)
#pragma unroll
            for (int q = 0; q < 4; q++) c[im][it][q] = 0.f;

    auto issue = [&](int s) {
        int pr = s >> 2, ch = s & 3, buf = s & 1;
        uint32_t sA = (uint32_t)__cvta_generic_to_shared(&As[buf][0]);
        uint32_t sB = (uint32_t)__cvta_generic_to_shared(&Bs[buf][0]);
        const float* Ap = P.A[pr];
        const float* Bp = P.B[pr];
#pragma unroll
        for (int i = 0; i < 4; i++) {
            int fi = tid + 128 * i;
            int row = fi >> 3, c4 = fi & 7;
            int ar = bm + row; if (ar > N_ - 1) ar = N_ - 1;
            cp16(sA + (uint32_t)(row * AS_STRIDE + c4 * 4) * 4,
                 Ap + ar * F_ + ch * 32 + c4 * 4);
        }
#pragma unroll
        for (int i = 0; i < 4; i++) {
            int fi = tid + 128 * i;
            int row = fi >> 4, c4 = fi & 15;
            cp16(sB + (uint32_t)(row * BS_STRIDE + c4 * 4) * 4,
                 Bp + (ch * 32 + row) * H_ + bn + c4 * 4);
        }
        asm volatile("cp.async.commit_group;\n" ::: "memory");
    };

    issue(0);
#pragma unroll 1
    for (int s = 0; s < 12; s++) {
        if (s + 1 < 12) {
            issue(s + 1);
            asm volatile("cp.async.wait_group 1;\n" ::: "memory");
        } else {
            asm volatile("cp.async.wait_group 0;\n" ::: "memory");
        }
        __syncthreads();
        const float* As_ = As[s & 1];
        const float* Bs_ = Bs[s & 1];
#pragma unroll
        for (int ks = 0; ks < 4; ks++) {
            const int k = ks * 8;
            uint32_t a[2][4];
#pragma unroll
            for (int im = 0; im < 2; im++) {
                int r0 = wm * 32 + im * 16 + g;
                a[im][0] = f2tf32(As_[r0 * AS_STRIDE + k + tig]);
                a[im][1] = f2tf32(As_[(r0 + 8) * AS_STRIDE + k + tig]);
                a[im][2] = f2tf32(As_[r0 * AS_STRIDE + k + tig + 4]);
                a[im][3] = f2tf32(As_[(r0 + 8) * AS_STRIDE + k + tig + 4]);
            }
            uint32_t b[4][2];
#pragma unroll
            for (int it = 0; it < 4; it++) {
                int cb = wn * 32 + it * 8 + g;
                b[it][0] = __float_as_uint(Bs_[(k + tig) * BS_STRIDE + cb]);
                b[it][1] = __float_as_uint(Bs_[(k + tig + 4) * BS_STRIDE + cb]);
            }
#pragma unroll
            for (int im = 0; im < 2; im++)
#pragma unroll
                for (int it = 0; it < 4; it++) mma_tf32(c[im][it], a[im], b[it]);
        }
        __syncthreads();
    }

#pragma unroll
    for (int im = 0; im < 2; im++) {
        int rbase = bm + wm * 32 + im * 16 + g;
#pragma unroll
        for (int half = 0; half < 2; half++) {
            int row = rbase + half * 8;
            if (row >= N_) continue;
#pragma unroll
            for (int it = 0; it < 4; it++) {
#pragma unroll
                for (int q = 0; q < 2; q++) {
                    int col = bn + wn * 32 + it * 8 + 2 * tig + q;
                    int idx = row * H_ + col;
                    float v = c[im][it][half * 2 + q] + __ldg(P.b + col) + P.xh[idx];
                    float zz = P.z[idx];
                    P.out[idx] = zz * P.h[idx] + (1.f - zz) * tanhf(v);
                }
            }
        }
    }
}

// ---------------- output projection (+ state reset on final step) ----------------
__global__ void k_proj(const float* __restrict__ h, const float* __restrict__ Wl,
                       const float* __restrict__ bl, float* __restrict__ out, int zero_h) {
    int n = blockIdx.x * 8 + (threadIdx.x >> 5);
    if (n >= N_) return;
    int lane = threadIdx.x & 31;
    float4 a = *(const float4*)(h + n * H_ + lane * 4);
    float4 w = *(const float4*)(Wl + lane * 4);
    float s = a.x * w.x + a.y * w.y + a.z * w.z + a.w * w.w;
#pragma unroll
    for (int o = 16; o; o >>= 1) s += __shfl_down_sync(0xffffffffu, s, o);
    if (lane == 0) out[n] = s + bl[0];
    if (zero_h) {   // restore h=0 for the next replay (deterministic self-reset)
        *(float4*)((float*)h + n * H_ + lane * 4) = make_float4(0.f, 0.f, 0.f, 0.f);
    }
}

// ---------------- driver ----------------
extern "C" void kernel_launch(void* const* d_in, const int* in_sizes, int n_in,
                              void* d_out, int out_size) {
    const float* x_seq = (const float*)d_in[0];
    const void*  ei    = d_in[1];
    const float* Wxz = (const float*)d_in[2];  const float* bxz = (const float*)d_in[3];
    const float* Whz = (const float*)d_in[4];  const float* bhz = (const float*)d_in[5];
    const float* Wxr = (const float*)d_in[6];  const float* bxr = (const float*)d_in[7];
    const float* Whr = (const float*)d_in[8];  const float* bhr = (const float*)d_in[9];
    const float* Wxh = (const float*)d_in[10]; const float* bxh = (const float*)d_in[11];
    const float* Whh = (const float*)d_in[12]; const float* bhh = (const float*)d_in[13];
    const float* Wl  = (const float*)d_in[14]; const float* bl  = (const float*)d_in[15];
    float* out = (float*)d_out;

    float *TxB1, *TxB2, *XZ, *XR, *XH, *Th1, *Th2, *Ts1, *Ts2, *h, *z, *s, *gW;
    cudaGetSymbolAddress((void**)&TxB1, g_TxB1);
    cudaGetSymbolAddress((void**)&TxB2, g_TxB2);
    cudaGetSymbolAddress((void**)&XZ,  g_XZ);
    cudaGetSymbolAddress((void**)&XR,  g_XR);
    cudaGetSymbolAddress((void**)&XH,  g_XH);
    cudaGetSymbolAddress((void**)&Th1, g_Th1);
    cudaGetSymbolAddress((void**)&Th2, g_Th2);
    cudaGetSymbolAddress((void**)&Ts1, g_Ts1);
    cudaGetSymbolAddress((void**)&Ts2, g_Ts2);
    cudaGetSymbolAddress((void**)&h,   g_h);
    cudaGetSymbolAddress((void**)&z,   g_z);
    cudaGetSymbolAddress((void**)&s,   g_s);
    cudaGetSymbolAddress((void**)&gW,  g_W);

    const int ZR_SMEM = (2 * AS_WORDS + 4 * BS_WORDS) * 4;   // 55296 B
    static int attr_done = 0;
    if (!attr_done) {
        cudaFuncSetAttribute(k_gemm_zr, cudaFuncAttributeMaxDynamicSharedMemorySize, ZR_SMEM);
        attr_done = 1;
    }

    // preprocessing: 3 launches (profiled 4th launch = hot batched prop)
    W6 w6; w6.p[0] = Wxz; w6.p[1] = Whz; w6.p[2] = Wxr; w6.p[3] = Whr; w6.p[4] = Wxh; w6.p[5] = Whh;
    k_count<<<(E_ + 255) / 256, 256>>>(ei, w6);
    k_scan <<<1, 1024>>>();
    k_fill <<<(E_ + 255) / 256, 256>>>(ei);

    const int WK = F_ * H_;
    const int GB = (N_ + 63) / 64;        // 157

    // ---- hoisted x-side: batched chains + batched 3-gate GEMM ----
    k_propb<<<dim3(N_, T_), H_>>>(x_seq, TxB1, nullptr, 1.f, 1);
    k_propb<<<dim3(N_, T_), H_>>>(TxB1, TxB2, x_seq,   2.f, 0);

    GX gx;
    gx.A[0] = x_seq; gx.A[1] = TxB1; gx.A[2] = TxB2;
    for (int k = 0; k < 3; k++) {
        gx.B[0][k] = Wxz + k * WK;   // fp32 weights fine: mma reads pre-rounded? use g_W x-slices
        gx.B[1][k] = Wxr + k * WK;
        gx.B[2][k] = Wxh + k * WK;
    }
    // use tf32-pre-rounded copies instead (consistent precision):
    gx.B[0][0] = gW + 0 * WSLICE + 0 * WK; gx.B[0][1] = gW + 0 * WSLICE + 1 * WK; gx.B[0][2] = gW + 0 * WSLICE + 2 * WK;
    gx.B[1][0] = gW + 2 * WSLICE + 0 * WK; gx.B[1][1] = gW + 2 * WSLICE + 1 * WK; gx.B[1][2] = gW + 2 * WSLICE + 2 * WK;
    gx.B[2][0] = gW + 4 * WSLICE + 0 * WK; gx.B[2][1] = gW + 4 * WSLICE + 1 * WK; gx.B[2][2] = gW + 4 * WSLICE + 2 * WK;
    gx.bias[0] = bxz; gx.bias[1] = bxr; gx.bias[2] = bxh;
    gx.out[0] = XZ; gx.out[1] = XR; gx.out[2] = XH;
    gx.M = T_ * N_;
    k_gemm_x<<<dim3((T_ * N_) / 64, 2, 3), 128>>>(gx);

    // ---- recurrence ----
    for (int t = 0; t < T_; t++) {
        k_propb<<<dim3(N_, 1), H_>>>(h,   Th1, nullptr, 1.f, 0);
        k_propb<<<dim3(N_, 1), H_>>>(Th1, Th2, h,       2.f, 0);

        GZR zr;
        zr.A[0] = h; zr.A[1] = Th1; zr.A[2] = Th2;
        for (int k = 0; k < 3; k++) {
            zr.Bz[k] = gW + 1 * WSLICE + k * WK;   // Whz
            zr.Br[k] = gW + 3 * WSLICE + k * WK;   // Whr
        }
        zr.bz = bhz; zr.br = bhr;
        zr.xz = XZ + (size_t)t * NH; zr.xr = XR + (size_t)t * NH;
        zr.h = h; zr.zout = z; zr.sout = s;
        k_gemm_zr<<<dim3(GB, 2), 128, ZR_SMEM>>>(zr);

        k_propb<<<dim3(N_, 1), H_>>>(s,   Ts1, nullptr, 1.f, 0);
        k_propb<<<dim3(N_, 1), H_>>>(Ts1, Ts2, s,       2.f, 0);

        GH gh;
        gh.A[0] = s; gh.A[1] = Ts1; gh.A[2] = Ts2;
        for (int k = 0; k < 3; k++) gh.B[k] = gW + 5 * WSLICE + k * WK;   // Whh
        gh.b = bhh; gh.xh = XH + (size_t)t * NH;
        gh.h = h; gh.z = z; gh.out = h;
        k_gemm_h<<<dim3(GB, 2), 128>>>(gh);

        k_proj<<<(N_ + 7) / 8, 256>>>(h, Wl, bl, out + t * N_, t == T_ - 1);
    }
    (void)in_sizes; (void)n_in; (void)out_size;
}

// round 7
// speedup vs baseline: 1.2495x; 1.2495x over previous
#include <cuda_runtime.h>
#include <cstdint>

#define T_ 12
#define N_ 10000
#define F_ 128
#define H_ 128
#define E_ 320000
#define NH (N_*H_)
#define TNH (T_*NH)
#define WSLICE (3*F_*H_)        // 49152 floats per gate weight tensor

// ---------------- scratch (static device memory; zero-initialized at load) ----------------
__device__ __align__(16) float g_TxB1[TNH];   // batched x-chain hop1 (all steps)
__device__ __align__(16) float g_TxB2[TNH];   // batched x-chain hop2
__device__ __align__(16) float g_Th1[NH];
__device__ __align__(16) float g_Th2[NH];
__device__ __align__(16) float g_Ts1[NH];
__device__ __align__(16) float g_Ts2[NH];
__device__ __align__(16) float g_h  [NH];     // zero-init; re-zeroed by final k_proj
__device__ __align__(16) float g_z  [NH];
__device__ __align__(16) float g_s  [NH];
__device__ __align__(16) float g_W  [6 * WSLICE];   // tf32-rounded weights
__device__ float g_deg[N_];       // zero-init; re-zeroed by first batched prop
__device__ int   g_cnt[N_];       // zero-init; re-zeroed by first batched prop
__device__ int   g_rowptr[N_ + 1];
__device__ int   g_wr[N_];        // write cursors for CSR fill
__device__ __align__(16) int2 g_cv[E_];   // packed CSR edge: {src col, val bits}

// per-thread edge dtype probe: int64 values < 2^32 -> odd int32 words all zero
__device__ __forceinline__ bool probe_is64(const void* ei) {
    const int* p = (const int*)ei;
    int acc = 0;
#pragma unroll
    for (int i = 1; i < 32; i += 2) acc |= p[i];
    return acc == 0;
}
__device__ __forceinline__ int edge_at(const void* ei, int idx, bool is64) {
    if (is64) return (int)((const long long*)ei)[idx];
    return ((const int*)ei)[idx];
}

// ---------------- preprocessing (3 launches) ----------------
struct W6 { const float* p[6]; };
__global__ void k_count(const void* __restrict__ ei, W6 w) {
    int e = blockIdx.x * blockDim.x + threadIdx.x;
    if (e < 6 * WSLICE) {
        int which = e / WSLICE;
        int off = e - which * WSLICE;
        float v = w.p[which][off];
        uint32_t r;
        asm("cvt.rna.tf32.f32 %0, %1;" : "=r"(r) : "f"(v));
        g_W[e] = __uint_as_float(r);
    }
    if (e >= E_) return;
    bool is64 = probe_is64(ei);
    int s = edge_at(ei, e, is64);
    int d = edge_at(ei, E_ + e, is64);
    if ((unsigned)s >= N_ || (unsigned)d >= N_) return;
    atomicAdd(&g_deg[s], 1.0f);
    atomicAdd(&g_cnt[d], 1);
}

// dinv + exclusive prefix sum + write-cursor init (single block, 1024 threads)
__global__ void k_scan() {
    __shared__ int sh[1024];
    int tid = threadIdx.x;
    for (int i = tid; i < N_; i += 1024) {
        float d = g_deg[i];
        g_deg[i] = (d > 0.f) ? rsqrtf(d) : 0.f;
    }
    const int PER = (N_ + 1023) / 1024;
    int base = tid * PER;
    int s = 0;
    for (int i = 0; i < PER; i++) { int ix = base + i; if (ix < N_) s += g_cnt[ix]; }
    sh[tid] = s;
    __syncthreads();
    for (int off = 1; off < 1024; off <<= 1) {
        int v = (tid >= off) ? sh[tid - off] : 0;
        __syncthreads();
        if (tid >= off) sh[tid] += v;
        __syncthreads();
    }
    int run = (tid > 0) ? sh[tid - 1] : 0;
    for (int i = 0; i < PER; i++) {
        int ix = base + i;
        if (ix < N_) { g_rowptr[ix] = run; g_wr[ix] = run; run += g_cnt[ix]; }
    }
    if (tid == 0) g_rowptr[N_] = sh[1023];
}

__global__ void k_fill(const void* __restrict__ ei) {
    int e = blockIdx.x * blockDim.x + threadIdx.x;
    if (e >= E_) return;
    bool is64 = probe_is64(ei);
    int s = edge_at(ei, e, is64);
    int d = edge_at(ei, E_ + e, is64);
    if ((unsigned)s >= N_ || (unsigned)d >= N_) return;
    int slot = atomicAdd(&g_wr[d], 1);
    float v = -g_deg[s] * g_deg[d];
    g_cv[slot] = make_int2(s, __float_as_int(v));
}

// ---------------- vectorized graph propagation (warp-per-node, float4 lanes) ----------------
// out[t,n,:] = scale * sum_e val*in[t,col,:] - sub[t,n,:]
// grid (1250, n_steps); 256 threads = 8 warps = 8 nodes; lane j holds features 4j..4j+3.
__global__ __launch_bounds__(256) void k_propv(const float* __restrict__ in,
                                               float* __restrict__ out,
                                               const float* __restrict__ sub,
                                               float scale, int clear) {
    const int lane = threadIdx.x & 31;
    const int n = blockIdx.x * 8 + (threadIdx.x >> 5);
    const int t = blockIdx.y;
    if (clear && t == 0 && lane == 0) { g_cnt[n] = 0; g_deg[n] = 0.f; }
    const size_t off4 = (size_t)t * (NH / 4);
    const float4* in4 = (const float4*)in + off4;
    float4* out4 = (float4*)out + off4;
    int e = g_rowptr[n];
    const int end = g_rowptr[n + 1];

    float4 a0 = make_float4(0.f, 0.f, 0.f, 0.f);
    float4 a1 = make_float4(0.f, 0.f, 0.f, 0.f);
#pragma unroll 1
    for (; e + 2 <= end; e += 2) {
        int2 cv0 = g_cv[e];
        int2 cv1 = g_cv[e + 1];
        float w0 = __int_as_float(cv0.y);
        float w1 = __int_as_float(cv1.y);
        float4 v0 = __ldg(in4 + cv0.x * 32 + lane);
        float4 v1 = __ldg(in4 + cv1.x * 32 + lane);
        a0.x += w0 * v0.x; a0.y += w0 * v0.y; a0.z += w0 * v0.z; a0.w += w0 * v0.w;
        a1.x += w1 * v1.x; a1.y += w1 * v1.y; a1.z += w1 * v1.z; a1.w += w1 * v1.w;
    }
    if (e < end) {
        int2 cv = g_cv[e];
        float w = __int_as_float(cv.y);
        float4 v = __ldg(in4 + cv.x * 32 + lane);
        a0.x += w * v.x; a0.y += w * v.y; a0.z += w * v.z; a0.w += w * v.w;
    }
    float4 r;
    r.x = scale * (a0.x + a1.x);
    r.y = scale * (a0.y + a1.y);
    r.z = scale * (a0.z + a1.z);
    r.w = scale * (a0.w + a1.w);
    const int oidx = n * 32 + lane;
    if (sub) {
        float4 sb = __ldg((const float4*)sub + off4 + oidx);
        r.x -= sb.x; r.y -= sb.y; r.z -= sb.z; r.w -= sb.w;
    }
    out4[oidx] = r;
}

// ---------------- tf32 tensor-core GEMMs ----------------
__device__ __forceinline__ float sigf(float x) { return 1.f / (1.f + expf(-x)); }
__device__ __forceinline__ void cp16(uint32_t dst, const void* src) {
    asm volatile("cp.async.cg.shared.global [%0], [%1], 16;\n" :: "r"(dst), "l"(src));
}
__device__ __forceinline__ uint32_t f2tf32(float v) {
    uint32_t r;
    asm("cvt.rna.tf32.f32 %0, %1;" : "=r"(r) : "f"(v));
    return r;
}
__device__ __forceinline__ void mma_tf32(float c[4], const uint32_t a[4], const uint32_t b[2]) {
    asm volatile(
        "mma.sync.aligned.m16n8k8.row.col.f32.tf32.tf32.f32 "
        "{%0,%1,%2,%3}, {%4,%5,%6,%7}, {%8,%9}, {%0,%1,%2,%3};\n"
        : "+f"(c[0]), "+f"(c[1]), "+f"(c[2]), "+f"(c[3])
        : "r"(a[0]), "r"(a[1]), "r"(a[2]), "r"(a[3]), "r"(b[0]), "r"(b[1]));
}

#define AS_STRIDE 36
#define BS_STRIDE 72
#define AS_WORDS (64 * AS_STRIDE)   // 2304
#define BS_WORDS (32 * BS_STRIDE)   // 2304

// ---- fused z + r GEMM (6 A pairs, two B pipelines) ----
struct GZR {
    const float* A[6];
    const float* Bz[6];
    const float* Br[6];
    const float* bz0; const float* bz1;
    const float* br0; const float* br1;
    const float* h;
    float* zout; float* sout;
};

__global__ __launch_bounds__(128) void k_gemm_zr(GZR P) {
    extern __shared__ float sm[];
    float* As = sm;
    float* Bz = sm + 2 * AS_WORDS;
    float* Br = sm + 2 * AS_WORDS + 2 * BS_WORDS;

    const int tid  = threadIdx.x;
    const int wid  = tid >> 5, lane = tid & 31;
    const int g    = lane >> 2, tig = lane & 3;
    const int wm   = wid >> 1, wn = wid & 1;
    const int bm   = blockIdx.x * 64;
    const int bn   = blockIdx.y * 64;

    float cz[2][4][4], cr[2][4][4];
#pragma unroll
    for (int im = 0; im < 2; im++)
#pragma unroll
        for (int it = 0; it < 4; it++)
#pragma unroll
            for (int q = 0; q < 4; q++) { cz[im][it][q] = 0.f; cr[im][it][q] = 0.f; }

    auto issue = [&](int s) {
        int pr = s >> 2, ch = s & 3, buf = s & 1;
        uint32_t sA = (uint32_t)__cvta_generic_to_shared(As + buf * AS_WORDS);
        uint32_t sZ = (uint32_t)__cvta_generic_to_shared(Bz + buf * BS_WORDS);
        uint32_t sR = (uint32_t)__cvta_generic_to_shared(Br + buf * BS_WORDS);
        const float* Ap = P.A[pr];
        const float* Zp = P.Bz[pr];
        const float* Rp = P.Br[pr];
#pragma unroll
        for (int i = 0; i < 4; i++) {
            int fi = tid + 128 * i;
            int row = fi >> 3, c4 = fi & 7;
            int ar = bm + row; if (ar > N_ - 1) ar = N_ - 1;
            cp16(sA + (uint32_t)(row * AS_STRIDE + c4 * 4) * 4,
                 Ap + ar * F_ + ch * 32 + c4 * 4);
        }
#pragma unroll
        for (int i = 0; i < 4; i++) {
            int fi = tid + 128 * i;
            int row = fi >> 4, c4 = fi & 15;
            cp16(sZ + (uint32_t)(row * BS_STRIDE + c4 * 4) * 4,
                 Zp + (ch * 32 + row) * H_ + bn + c4 * 4);
        }
#pragma unroll
        for (int i = 0; i < 4; i++) {
            int fi = tid + 128 * i;
            int row = fi >> 4, c4 = fi & 15;
            cp16(sR + (uint32_t)(row * BS_STRIDE + c4 * 4) * 4,
                 Rp + (ch * 32 + row) * H_ + bn + c4 * 4);
        }
        asm volatile("cp.async.commit_group;\n" ::: "memory");
    };

    issue(0);
#pragma unroll 1
    for (int s = 0; s < 24; s++) {            // 6 pairs x 4 k-chunks
        if (s + 1 < 24) {
            issue(s + 1);
            asm volatile("cp.async.wait_group 1;\n" ::: "memory");
        } else {
            asm volatile("cp.async.wait_group 0;\n" ::: "memory");
        }
        __syncthreads();
        const float* As_ = As + (s & 1) * AS_WORDS;
        const float* Bz_ = Bz + (s & 1) * BS_WORDS;
        const float* Br_ = Br + (s & 1) * BS_WORDS;
#pragma unroll
        for (int ks = 0; ks < 4; ks++) {
            const int k = ks * 8;
            uint32_t a[2][4];
#pragma unroll
            for (int im = 0; im < 2; im++) {
                int r0 = wm * 32 + im * 16 + g;
                a[im][0] = f2tf32(As_[r0 * AS_STRIDE + k + tig]);
                a[im][1] = f2tf32(As_[(r0 + 8) * AS_STRIDE + k + tig]);
                a[im][2] = f2tf32(As_[r0 * AS_STRIDE + k + tig + 4]);
                a[im][3] = f2tf32(As_[(r0 + 8) * AS_STRIDE + k + tig + 4]);
            }
            uint32_t bz[4][2], br[4][2];
#pragma unroll
            for (int it = 0; it < 4; it++) {
                int cb = wn * 32 + it * 8 + g;
                bz[it][0] = __float_as_uint(Bz_[(k + tig) * BS_STRIDE + cb]);
                bz[it][1] = __float_as_uint(Bz_[(k + tig + 4) * BS_STRIDE + cb]);
                br[it][0] = __float_as_uint(Br_[(k + tig) * BS_STRIDE + cb]);
                br[it][1] = __float_as_uint(Br_[(k + tig + 4) * BS_STRIDE + cb]);
            }
#pragma unroll
            for (int im = 0; im < 2; im++)
#pragma unroll
                for (int it = 0; it < 4; it++) {
                    mma_tf32(cz[im][it], a[im], bz[it]);
                    mma_tf32(cr[im][it], a[im], br[it]);
                }
        }
        __syncthreads();
    }

#pragma unroll
    for (int im = 0; im < 2; im++) {
        int rbase = bm + wm * 32 + im * 16 + g;
#pragma unroll
        for (int half = 0; half < 2; half++) {
            int row = rbase + half * 8;
            if (row >= N_) continue;
#pragma unroll
            for (int it = 0; it < 4; it++) {
#pragma unroll
                for (int q = 0; q < 2; q++) {
                    int col = bn + wn * 32 + it * 8 + 2 * tig + q;
                    int idx = row * H_ + col;
                    float vz = cz[im][it][half * 2 + q] + __ldg(P.bz0 + col) + __ldg(P.bz1 + col);
                    float vr = cr[im][it][half * 2 + q] + __ldg(P.br0 + col) + __ldg(P.br1 + col);
                    P.zout[idx] = sigf(vz);
                    P.sout[idx] = P.h[idx] * sigf(vr);
                }
            }
        }
    }
}

// ---- h-update GEMM (6 A pairs): h = z*h + (1-z)*tanh(sum A_p B_p + b0 + b1) ----
struct GP {
    const float* A[6];
    const float* B[6];
    const float* b0; const float* b1;
    const float* h;  const float* z;
    float* out;
};

__global__ __launch_bounds__(128) void k_gemm_h(GP P) {
    __shared__ float As[2][AS_WORDS];
    __shared__ float Bs[2][BS_WORDS];

    const int tid  = threadIdx.x;
    const int wid  = tid >> 5, lane = tid & 31;
    const int g    = lane >> 2, tig = lane & 3;
    const int wm   = wid >> 1, wn = wid & 1;
    const int bm   = blockIdx.x * 64;
    const int bn   = blockIdx.y * 64;

    float c[2][4][4];
#pragma unroll
    for (int im = 0; im < 2; im++)
#pragma unroll
        for (int it = 0; it < 4; it++)
#pragma unroll
            for (int q = 0; q < 4; q++) c[im][it][q] = 0.f;

    auto issue = [&](int s) {
        int pr = s >> 2, ch = s & 3, buf = s & 1;
        uint32_t sA = (uint32_t)__cvta_generic_to_shared(&As[buf][0]);
        uint32_t sB = (uint32_t)__cvta_generic_to_shared(&Bs[buf][0]);
        const float* Ap = P.A[pr];
        const float* Bp = P.B[pr];
#pragma unroll
        for (int i = 0; i < 4; i++) {
            int fi = tid + 128 * i;
            int row = fi >> 3, c4 = fi & 7;
            int ar = bm + row; if (ar > N_ - 1) ar = N_ - 1;
            cp16(sA + (uint32_t)(row * AS_STRIDE + c4 * 4) * 4,
                 Ap + ar * F_ + ch * 32 + c4 * 4);
        }
#pragma unroll
        for (int i = 0; i < 4; i++) {
            int fi = tid + 128 * i;
            int row = fi >> 4, c4 = fi & 15;
            cp16(sB + (uint32_t)(row * BS_STRIDE + c4 * 4) * 4,
                 Bp + (ch * 32 + row) * H_ + bn + c4 * 4);
        }
        asm volatile("cp.async.commit_group;\n" ::: "memory");
    };

    issue(0);
#pragma unroll 1
    for (int s = 0; s < 24; s++) {
        if (s + 1 < 24) {
            issue(s + 1);
            asm volatile("cp.async.wait_group 1;\n" ::: "memory");
        } else {
            asm volatile("cp.async.wait_group 0;\n" ::: "memory");
        }
        __syncthreads();
        const float* As_ = As[s & 1];
        const float* Bs_ = Bs[s & 1];
#pragma unroll
        for (int ks = 0; ks < 4; ks++) {
            const int k = ks * 8;
            uint32_t a[2][4];
#pragma unroll
            for (int im = 0; im < 2; im++) {
                int r0 = wm * 32 + im * 16 + g;
                a[im][0] = f2tf32(As_[r0 * AS_STRIDE + k + tig]);
                a[im][1] = f2tf32(As_[(r0 + 8) * AS_STRIDE + k + tig]);
                a[im][2] = f2tf32(As_[r0 * AS_STRIDE + k + tig + 4]);
                a[im][3] = f2tf32(As_[(r0 + 8) * AS_STRIDE + k + tig + 4]);
            }
            uint32_t b[4][2];
#pragma unroll
            for (int it = 0; it < 4; it++) {
                int cb = wn * 32 + it * 8 + g;
                b[it][0] = __float_as_uint(Bs_[(k + tig) * BS_STRIDE + cb]);
                b[it][1] = __float_as_uint(Bs_[(k + tig + 4) * BS_STRIDE + cb]);
            }
#pragma unroll
            for (int im = 0; im < 2; im++)
#pragma unroll
                for (int it = 0; it < 4; it++) mma_tf32(c[im][it], a[im], b[it]);
        }
        __syncthreads();
    }

#pragma unroll
    for (int im = 0; im < 2; im++) {
        int rbase = bm + wm * 32 + im * 16 + g;
#pragma unroll
        for (int half = 0; half < 2; half++) {
            int row = rbase + half * 8;
            if (row >= N_) continue;
#pragma unroll
            for (int it = 0; it < 4; it++) {
#pragma unroll
                for (int q = 0; q < 2; q++) {
                    int col = bn + wn * 32 + it * 8 + 2 * tig + q;
                    int idx = row * H_ + col;
                    float v = c[im][it][half * 2 + q] + __ldg(P.b0 + col) + __ldg(P.b1 + col);
                    float zz = P.z[idx];
                    P.out[idx] = zz * P.h[idx] + (1.f - zz) * tanhf(v);
                }
            }
        }
    }
}

// ---------------- output projection (+ state reset on final step) ----------------
__global__ void k_proj(const float* __restrict__ h, const float* __restrict__ Wl,
                       const float* __restrict__ bl, float* __restrict__ out, int zero_h) {
    int n = blockIdx.x * 8 + (threadIdx.x >> 5);
    if (n >= N_) return;
    int lane = threadIdx.x & 31;
    float4 a = *(const float4*)(h + n * H_ + lane * 4);
    float4 w = *(const float4*)(Wl + lane * 4);
    float s = a.x * w.x + a.y * w.y + a.z * w.z + a.w * w.w;
#pragma unroll
    for (int o = 16; o; o >>= 1) s += __shfl_down_sync(0xffffffffu, s, o);
    if (lane == 0) out[n] = s + bl[0];
    if (zero_h) {   // restore h=0 for the next replay (deterministic self-reset)
        *(float4*)((float*)h + n * H_ + lane * 4) = make_float4(0.f, 0.f, 0.f, 0.f);
    }
}

// ---------------- driver ----------------
extern "C" void kernel_launch(void* const* d_in, const int* in_sizes, int n_in,
                              void* d_out, int out_size) {
    const float* x_seq = (const float*)d_in[0];
    const void*  ei    = d_in[1];
    const float* Wxz = (const float*)d_in[2];  const float* bxz = (const float*)d_in[3];
    const float* Whz = (const float*)d_in[4];  const float* bhz = (const float*)d_in[5];
    const float* Wxr = (const float*)d_in[6];  const float* bxr = (const float*)d_in[7];
    const float* Whr = (const float*)d_in[8];  const float* bhr = (const float*)d_in[9];
    const float* Wxh = (const float*)d_in[10]; const float* bxh = (const float*)d_in[11];
    const float* Whh = (const float*)d_in[12]; const float* bhh = (const float*)d_in[13];
    const float* Wl  = (const float*)d_in[14]; const float* bl  = (const float*)d_in[15];
    float* out = (float*)d_out;

    float *TxB1, *TxB2, *Th1, *Th2, *Ts1, *Ts2, *h, *z, *s, *gW;
    cudaGetSymbolAddress((void**)&TxB1, g_TxB1);
    cudaGetSymbolAddress((void**)&TxB2, g_TxB2);
    cudaGetSymbolAddress((void**)&Th1, g_Th1);
    cudaGetSymbolAddress((void**)&Th2, g_Th2);
    cudaGetSymbolAddress((void**)&Ts1, g_Ts1);
    cudaGetSymbolAddress((void**)&Ts2, g_Ts2);
    cudaGetSymbolAddress((void**)&h,   g_h);
    cudaGetSymbolAddress((void**)&z,   g_z);
    cudaGetSymbolAddress((void**)&s,   g_s);
    cudaGetSymbolAddress((void**)&gW,  g_W);

    const int ZR_SMEM = (2 * AS_WORDS + 4 * BS_WORDS) * 4;   // 55296 B
    static int attr_done = 0;
    if (!attr_done) {
        cudaFuncSetAttribute(k_gemm_zr, cudaFuncAttributeMaxDynamicSharedMemorySize, ZR_SMEM);
        attr_done = 1;
    }

    // preprocessing: 3 launches (profiled 4th launch = hot vectorized batched prop)
    W6 w6; w6.p[0] = Wxz; w6.p[1] = Whz; w6.p[2] = Wxr; w6.p[3] = Whr; w6.p[4] = Wxh; w6.p[5] = Whh;
    k_count<<<(E_ + 255) / 256, 256>>>(ei, w6);
    k_scan <<<1, 1024>>>();
    k_fill <<<(E_ + 255) / 256, 256>>>(ei);

    const int WK = F_ * H_;
    const int GB = (N_ + 63) / 64;        // 157
    const int PB = N_ / 8;                // 1250 prop blocks

    // ---- batched x-chain props (no gate materialization) ----
    k_propv<<<dim3(PB, T_), 256>>>(x_seq, TxB1, nullptr, 1.f, 1);
    k_propv<<<dim3(PB, T_), 256>>>(TxB1, TxB2, x_seq,   2.f, 0);

    // ---- recurrence ----
    for (int t = 0; t < T_; t++) {
        const float* xt  = x_seq + (size_t)t * NH;
        const float* tx1 = TxB1  + (size_t)t * NH;
        const float* tx2 = TxB2  + (size_t)t * NH;

        k_propv<<<dim3(PB, 1), 256>>>(h,   Th1, nullptr, 1.f, 0);
        k_propv<<<dim3(PB, 1), 256>>>(Th1, Th2, h,       2.f, 0);

        GZR zr;
        zr.A[0] = xt; zr.A[1] = tx1; zr.A[2] = tx2;
        zr.A[3] = h;  zr.A[4] = Th1; zr.A[5] = Th2;
        for (int k = 0; k < 3; k++) {
            zr.Bz[k] = gW + 0 * WSLICE + k * WK; zr.Bz[3 + k] = gW + 1 * WSLICE + k * WK;
            zr.Br[k] = gW + 2 * WSLICE + k * WK; zr.Br[3 + k] = gW + 3 * WSLICE + k * WK;
        }
        zr.bz0 = bxz; zr.bz1 = bhz; zr.br0 = bxr; zr.br1 = bhr;
        zr.h = h; zr.zout = z; zr.sout = s;
        k_gemm_zr<<<dim3(GB, 2), 128, ZR_SMEM>>>(zr);

        k_propv<<<dim3(PB, 1), 256>>>(s,   Ts1, nullptr, 1.f, 0);
        k_propv<<<dim3(PB, 1), 256>>>(Ts1, Ts2, s,       2.f, 0);

        GP ph;
        ph.A[0] = xt; ph.A[1] = tx1; ph.A[2] = tx2;
        ph.A[3] = s;  ph.A[4] = Ts1; ph.A[5] = Ts2;
        for (int k = 0; k < 3; k++) {
            ph.B[k] = gW + 4 * WSLICE + k * WK; ph.B[3 + k] = gW + 5 * WSLICE + k * WK;
        }
        ph.b0 = bxh; ph.b1 = bhh; ph.out = h; ph.h = h; ph.z = z;
        k_gemm_h<<<dim3(GB, 2), 128>>>(ph);

        k_proj<<<(N_ + 7) / 8, 256>>>(h, Wl, bl, out + t * N_, t == T_ - 1);
    }
    (void)in_sizes; (void)n_in; (void)out_size;
}

// round 8
// speedup vs baseline: 1.4468x; 1.1580x over previous
#include <cuda_runtime.h>
#include <cuda_fp16.h>
#include <cstdint>

#define T_ 12
#define N_ 10000
#define F_ 128
#define H_ 128
#define E_ 320000
#define NH (N_*H_)
#define TNH (T_*NH)
#define WSLICE (3*F_*H_)        // 49152 floats per gate weight tensor

// ---------------- scratch (static device memory; zero-initialized at load) ----------------
__device__ __align__(16) float  g_TxB1[TNH];    // x-chain hop1 fp32 (hop2 input)
__device__ __align__(16) __half g_x16 [TNH];    // fp16 shadow of x_seq
__device__ __align__(16) __half g_TxB1h[TNH];   // fp16 shadows (GEMM A operands)
__device__ __align__(16) __half g_TxB2h[TNH];
__device__ __align__(16) float  g_Th1[NH];
__device__ __align__(16) __half g_Th1h[NH];
__device__ __align__(16) __half g_Th2h[NH];
__device__ __align__(16) float  g_Ts1[NH];
__device__ __align__(16) __half g_Ts1h[NH];
__device__ __align__(16) __half g_Ts2h[NH];
__device__ __align__(16) float  g_h  [NH];      // fp32 master state
__device__ __align__(16) __half g_h16[NH];
__device__ __align__(16) float  g_z  [NH];
__device__ __align__(16) float  g_s  [NH];      // s = h*r fp32 (prop input / hop2 sub)
__device__ __align__(16) __half g_s16[NH];
__device__ __align__(16) __half g_Wt [6 * WSLICE];  // fp16 weights, transposed [gate*3+k][n][k]
__device__ float g_deg[N_];
__device__ int   g_cnt[N_];
__device__ int   g_rowptr[N_ + 1];
__device__ int   g_wr[N_];
__device__ __align__(16) int2 g_cv[E_];   // packed CSR edge: {src*32, val bits}

__device__ __forceinline__ bool probe_is64(const void* ei) {
    const int* p = (const int*)ei;
    int acc = 0;
#pragma unroll
    for (int i = 1; i < 32; i += 2) acc |= p[i];
    return acc == 0;
}
__device__ __forceinline__ int edge_at(const void* ei, int idx, bool is64) {
    if (is64) return (int)((const long long*)ei)[idx];
    return ((const int*)ei)[idx];
}

// ---------------- preprocessing (3 launches) ----------------
// edge counting + weight fp16 transpose + x_seq fp16 conversion
struct W6 { const float* p[6]; };
__global__ void k_count(const void* __restrict__ ei, const float* __restrict__ x_seq, W6 w) {
    int e = blockIdx.x * blockDim.x + threadIdx.x;     // 320000 threads
    if (e < 6 * WSLICE) {                              // transpose W[k][n] -> Wt[n][k], fp16
        int which = e / WSLICE;
        int r = e - which * WSLICE;
        int slice = r / (F_ * H_);
        int r2 = r - slice * (F_ * H_);
        int n = r2 >> 7, k = r2 & 127;
        g_Wt[e] = __float2half(w.p[which][slice * F_ * H_ + k * H_ + n]);
    }
    // x_seq -> fp16 shadow (grid-stride over float4)
    const float4* x4 = (const float4*)x_seq;
    uint2* o16 = (uint2*)g_x16;
    for (int i = e; i < TNH / 4; i += 320000) {
        float4 v = x4[i];
        __half2 p0 = __floats2half2_rn(v.x, v.y);
        __half2 p1 = __floats2half2_rn(v.z, v.w);
        uint2 u; u.x = *(uint32_t*)&p0; u.y = *(uint32_t*)&p1;
        o16[i] = u;
    }
    if (e >= E_) return;
    bool is64 = probe_is64(ei);
    int s = edge_at(ei, e, is64);
    int d = edge_at(ei, E_ + e, is64);
    if ((unsigned)s >= N_ || (unsigned)d >= N_) return;
    atomicAdd(&g_deg[s], 1.0f);
    atomicAdd(&g_cnt[d], 1);
}

// dinv + exclusive prefix sum + write cursors (single block, 1024 threads)
__global__ void k_scan() {
    __shared__ int sh[1024];
    int tid = threadIdx.x;
    for (int i = tid; i < N_; i += 1024) {
        float d = g_deg[i];
        g_deg[i] = (d > 0.f) ? rsqrtf(d) : 0.f;
    }
    const int PER = (N_ + 1023) / 1024;
    int base = tid * PER;
    int s = 0;
    for (int i = 0; i < PER; i++) { int ix = base + i; if (ix < N_) s += g_cnt[ix]; }
    sh[tid] = s;
    __syncthreads();
    for (int off = 1; off < 1024; off <<= 1) {
        int v = (tid >= off) ? sh[tid - off] : 0;
        __syncthreads();
        if (tid >= off) sh[tid] += v;
        __syncthreads();
    }
    int run = (tid > 0) ? sh[tid - 1] : 0;
    for (int i = 0; i < PER; i++) {
        int ix = base + i;
        if (ix < N_) { g_rowptr[ix] = run; g_wr[ix] = run; run += g_cnt[ix]; }
    }
    if (tid == 0) g_rowptr[N_] = sh[1023];
}

__global__ void k_fill(const void* __restrict__ ei) {
    int e = blockIdx.x * blockDim.x + threadIdx.x;
    if (e >= E_) return;
    bool is64 = probe_is64(ei);
    int s = edge_at(ei, e, is64);
    int d = edge_at(ei, E_ + e, is64);
    if ((unsigned)s >= N_ || (unsigned)d >= N_) return;
    int slot = atomicAdd(&g_wr[d], 1);
    float v = -g_deg[s] * g_deg[d];
    g_cv[slot] = make_int2(s * 32, __float_as_int(v));   // pre-scaled col (float4 units)
}

// ---------------- vectorized graph propagation (fp32 gather, dual fp32+fp16 output) ----------------
// out[t,n,:]  = scale*sum val*in[t,col,:] - sub[t,n,:]   (out nullable; out16 always written)
__global__ __launch_bounds__(256) void k_propv(const float* __restrict__ in,
                                               float* __restrict__ out,
                                               __half* __restrict__ out16,
                                               const float* __restrict__ sub,
                                               float scale, int clear) {
    const int lane = threadIdx.x & 31;
    const int n = blockIdx.x * 8 + (threadIdx.x >> 5);
    const int t = blockIdx.y;
    if (clear && t == 0 && lane == 0) { g_cnt[n] = 0; g_deg[n] = 0.f; }
    const size_t off4 = (size_t)t * (NH / 4);
    const float4* in4 = (const float4*)in + off4;
    int e = g_rowptr[n];
    const int end = g_rowptr[n + 1];

    float4 a0 = make_float4(0.f, 0.f, 0.f, 0.f);
    float4 a1 = make_float4(0.f, 0.f, 0.f, 0.f);
#pragma unroll 1
    for (; e + 2 <= end; e += 2) {
        int2 cv0 = g_cv[e];
        int2 cv1 = g_cv[e + 1];
        float w0 = __int_as_float(cv0.y);
        float w1 = __int_as_float(cv1.y);
        float4 v0 = __ldg(in4 + cv0.x + lane);
        float4 v1 = __ldg(in4 + cv1.x + lane);
        a0.x += w0 * v0.x; a0.y += w0 * v0.y; a0.z += w0 * v0.z; a0.w += w0 * v0.w;
        a1.x += w1 * v1.x; a1.y += w1 * v1.y; a1.z += w1 * v1.z; a1.w += w1 * v1.w;
    }
    if (e < end) {
        int2 cv = g_cv[e];
        float w = __int_as_float(cv.y);
        float4 v = __ldg(in4 + cv.x + lane);
        a0.x += w * v.x; a0.y += w * v.y; a0.z += w * v.z; a0.w += w * v.w;
    }
    float4 r;
    r.x = scale * (a0.x + a1.x);
    r.y = scale * (a0.y + a1.y);
    r.z = scale * (a0.z + a1.z);
    r.w = scale * (a0.w + a1.w);
    const int oidx = n * 32 + lane;
    if (sub) {
        float4 sb = __ldg((const float4*)sub + off4 + oidx);
        r.x -= sb.x; r.y -= sb.y; r.z -= sb.z; r.w -= sb.w;
    }
    if (out) ((float4*)out + off4)[oidx] = r;
    __half2 p0 = __floats2half2_rn(r.x, r.y);
    __half2 p1 = __floats2half2_rn(r.z, r.w);
    uint2 u; u.x = *(uint32_t*)&p0; u.y = *(uint32_t*)&p1;
    ((uint2*)out16 + off4)[oidx] = u;
}

// ---------------- fp16 tensor-core GEMMs (m16n8k16, fp32 accum) ----------------
__device__ __forceinline__ float sigf(float x) { return 1.f / (1.f + expf(-x)); }
__device__ __forceinline__ void cp16(uint32_t dst, const void* src) {
    asm volatile("cp.async.cg.shared.global [%0], [%1], 16;\n" :: "r"(dst), "l"(src));
}
__device__ __forceinline__ void mma_f16(float c[4], const uint32_t a[4], const uint32_t b[2]) {
    asm volatile(
        "mma.sync.aligned.m16n8k16.row.col.f32.f16.f16.f32 "
        "{%0,%1,%2,%3}, {%4,%5,%6,%7}, {%8,%9}, {%0,%1,%2,%3};\n"
        : "+f"(c[0]), "+f"(c[1]), "+f"(c[2]), "+f"(c[3])
        : "r"(a[0]), "r"(a[1]), "r"(a[2]), "r"(a[3]), "r"(b[0]), "r"(b[1]));
}

#define HS 40                 // halves per smem row (32 data + 8 pad; banks conflict-free)
#define TILE_H (64 * HS)      // 2560 halves = 5120 B per tile

// ---- fused z + r GEMM ----
struct GZR {
    const __half* A[6];
    const __half* Bz[6];
    const __half* Br[6];
    const float* bz0; const float* bz1;
    const float* br0; const float* br1;
    const float* h;
    float* zout; float* sout; __half* sout16;
};

__global__ __launch_bounds__(128) void k_gemm_zr(GZR P) {
    __shared__ __half As[2][TILE_H], Bzs[2][TILE_H], Brs[2][TILE_H];

    const int tid  = threadIdx.x;
    const int wid  = tid >> 5, lane = tid & 31;
    const int g    = lane >> 2, tig = lane & 3;
    const int wm   = wid >> 1, wn = wid & 1;
    const int bm   = blockIdx.x * 64;
    const int bn   = blockIdx.y * 64;

    float cz[2][4][4], cr[2][4][4];
#pragma unroll
    for (int im = 0; im < 2; im++)
#pragma unroll
        for (int it = 0; it < 4; it++)
#pragma unroll
            for (int q = 0; q < 4; q++) { cz[im][it][q] = 0.f; cr[im][it][q] = 0.f; }

    auto issue = [&](int s) {
        int pr = s >> 2, ch = s & 3, buf = s & 1;
        uint32_t sA = (uint32_t)__cvta_generic_to_shared(&As[buf][0]);
        uint32_t sZ = (uint32_t)__cvta_generic_to_shared(&Bzs[buf][0]);
        uint32_t sR = (uint32_t)__cvta_generic_to_shared(&Brs[buf][0]);
        const __half* Ap = P.A[pr];
        const __half* Zp = P.Bz[pr];
        const __half* Rp = P.Br[pr];
#pragma unroll
        for (int i = 0; i < 2; i++) {            // 64 rows x 4 chunks of 16B
            int fi = tid + 128 * i;
            int row = fi >> 2, c8 = fi & 3;
            int ar = bm + row; if (ar > N_ - 1) ar = N_ - 1;
            uint32_t so = (uint32_t)(row * HS + c8 * 8) * 2;
            cp16(sA + so, Ap + (size_t)ar * H_ + ch * 32 + c8 * 8);
            cp16(sZ + so, Zp + (bn + row) * H_ + ch * 32 + c8 * 8);
            cp16(sR + so, Rp + (bn + row) * H_ + ch * 32 + c8 * 8);
        }
        asm volatile("cp.async.commit_group;\n" ::: "memory");
    };

    issue(0);
#pragma unroll 1
    for (int s = 0; s < 24; s++) {               // 6 pairs x 4 k-chunks of 32
        if (s + 1 < 24) {
            issue(s + 1);
            asm volatile("cp.async.wait_group 1;\n" ::: "memory");
        } else {
            asm volatile("cp.async.wait_group 0;\n" ::: "memory");
        }
        __syncthreads();
        const __half* As_ = As[s & 1];
        const __half* Bz_ = Bzs[s & 1];
        const __half* Br_ = Brs[s & 1];
#pragma unroll
        for (int ks = 0; ks < 2; ks++) {
            const int k0 = ks * 16;
            uint32_t a[2][4];
#pragma unroll
            for (int im = 0; im < 2; im++) {
                int r0 = wm * 32 + im * 16 + g;
                a[im][0] = *(const uint32_t*)(As_ + r0 * HS + k0 + 2 * tig);
                a[im][1] = *(const uint32_t*)(As_ + (r0 + 8) * HS + k0 + 2 * tig);
                a[im][2] = *(const uint32_t*)(As_ + r0 * HS + k0 + 2 * tig + 8);
                a[im][3] = *(const uint32_t*)(As_ + (r0 + 8) * HS + k0 + 2 * tig + 8);
            }
            uint32_t bz[4][2], br[4][2];
#pragma unroll
            for (int it = 0; it < 4; it++) {
                int cb = wn * 32 + it * 8 + g;
                bz[it][0] = *(const uint32_t*)(Bz_ + cb * HS + k0 + 2 * tig);
                bz[it][1] = *(const uint32_t*)(Bz_ + cb * HS + k0 + 2 * tig + 8);
                br[it][0] = *(const uint32_t*)(Br_ + cb * HS + k0 + 2 * tig);
                br[it][1] = *(const uint32_t*)(Br_ + cb * HS + k0 + 2 * tig + 8);
            }
#pragma unroll
            for (int im = 0; im < 2; im++)
#pragma unroll
                for (int it = 0; it < 4; it++) {
                    mma_f16(cz[im][it], a[im], bz[it]);
                    mma_f16(cr[im][it], a[im], br[it]);
                }
        }
        __syncthreads();
    }

    // epilogue: z = sigmoid(vz); s = h * sigmoid(vr); s also to fp16
#pragma unroll
    for (int im = 0; im < 2; im++) {
        int rbase = bm + wm * 32 + im * 16 + g;
#pragma unroll
        for (int half = 0; half < 2; half++) {
            int row = rbase + half * 8;
            if (row >= N_) continue;
#pragma unroll
            for (int it = 0; it < 4; it++) {
                int col0 = bn + wn * 32 + it * 8 + 2 * tig;
                int idx = row * H_ + col0;
                float vz0 = cz[im][it][half * 2 + 0] + __ldg(P.bz0 + col0)     + __ldg(P.bz1 + col0);
                float vz1 = cz[im][it][half * 2 + 1] + __ldg(P.bz0 + col0 + 1) + __ldg(P.bz1 + col0 + 1);
                float vr0 = cr[im][it][half * 2 + 0] + __ldg(P.br0 + col0)     + __ldg(P.br1 + col0);
                float vr1 = cr[im][it][half * 2 + 1] + __ldg(P.br0 + col0 + 1) + __ldg(P.br1 + col0 + 1);
                float s0 = P.h[idx] * sigf(vr0);
                float s1 = P.h[idx + 1] * sigf(vr1);
                P.zout[idx] = sigf(vz0);
                P.zout[idx + 1] = sigf(vz1);
                P.sout[idx] = s0;
                P.sout[idx + 1] = s1;
                *(__half2*)(P.sout16 + idx) = __floats2half2_rn(s0, s1);
            }
        }
    }
}

// ---- h-update GEMM: h = z*h + (1-z)*tanh(acc + b0 + b1); h also to fp16 ----
struct GH {
    const __half* A[6];
    const __half* B[6];
    const float* b0; const float* b1;
    const float* h;  const float* z;
    float* out; __half* out16;
};

__global__ __launch_bounds__(128) void k_gemm_h(GH P) {
    __shared__ __half As[2][TILE_H], Bs[2][TILE_H];

    const int tid  = threadIdx.x;
    const int wid  = tid >> 5, lane = tid & 31;
    const int g    = lane >> 2, tig = lane & 3;
    const int wm   = wid >> 1, wn = wid & 1;
    const int bm   = blockIdx.x * 64;
    const int bn   = blockIdx.y * 64;

    float c[2][4][4];
#pragma unroll
    for (int im = 0; im < 2; im++)
#pragma unroll
        for (int it = 0; it < 4; it++)
#pragma unroll
            for (int q = 0; q < 4; q++) c[im][it][q] = 0.f;

    auto issue = [&](int s) {
        int pr = s >> 2, ch = s & 3, buf = s & 1;
        uint32_t sA = (uint32_t)__cvta_generic_to_shared(&As[buf][0]);
        uint32_t sB = (uint32_t)__cvta_generic_to_shared(&Bs[buf][0]);
        const __half* Ap = P.A[pr];
        const __half* Bp = P.B[pr];
#pragma unroll
        for (int i = 0; i < 2; i++) {
            int fi = tid + 128 * i;
            int row = fi >> 2, c8 = fi & 3;
            int ar = bm + row; if (ar > N_ - 1) ar = N_ - 1;
            uint32_t so = (uint32_t)(row * HS + c8 * 8) * 2;
            cp16(sA + so, Ap + (size_t)ar * H_ + ch * 32 + c8 * 8);
            cp16(sB + so, Bp + (bn + row) * H_ + ch * 32 + c8 * 8);
        }
        asm volatile("cp.async.commit_group;\n" ::: "memory");
    };

    issue(0);
#pragma unroll 1
    for (int s = 0; s < 24; s++) {
        if (s + 1 < 24) {
            issue(s + 1);
            asm volatile("cp.async.wait_group 1;\n" ::: "memory");
        } else {
            asm volatile("cp.async.wait_group 0;\n" ::: "memory");
        }
        __syncthreads();
        const __half* As_ = As[s & 1];
        const __half* Bs_ = Bs[s & 1];
#pragma unroll
        for (int ks = 0; ks < 2; ks++) {
            const int k0 = ks * 16;
            uint32_t a[2][4];
#pragma unroll
            for (int im = 0; im < 2; im++) {
                int r0 = wm * 32 + im * 16 + g;
                a[im][0] = *(const uint32_t*)(As_ + r0 * HS + k0 + 2 * tig);
                a[im][1] = *(const uint32_t*)(As_ + (r0 + 8) * HS + k0 + 2 * tig);
                a[im][2] = *(const uint32_t*)(As_ + r0 * HS + k0 + 2 * tig + 8);
                a[im][3] = *(const uint32_t*)(As_ + (r0 + 8) * HS + k0 + 2 * tig + 8);
            }
            uint32_t b[4][2];
#pragma unroll
            for (int it = 0; it < 4; it++) {
                int cb = wn * 32 + it * 8 + g;
                b[it][0] = *(const uint32_t*)(Bs_ + cb * HS + k0 + 2 * tig);
                b[it][1] = *(const uint32_t*)(Bs_ + cb * HS + k0 + 2 * tig + 8);
            }
#pragma unroll
            for (int im = 0; im < 2; im++)
#pragma unroll
                for (int it = 0; it < 4; it++) mma_f16(c[im][it], a[im], b[it]);
        }
        __syncthreads();
    }

#pragma unroll
    for (int im = 0; im < 2; im++) {
        int rbase = bm + wm * 32 + im * 16 + g;
#pragma unroll
        for (int half = 0; half < 2; half++) {
            int row = rbase + half * 8;
            if (row >= N_) continue;
#pragma unroll
            for (int it = 0; it < 4; it++) {
                int col0 = bn + wn * 32 + it * 8 + 2 * tig;
                int idx = row * H_ + col0;
                float v0 = c[im][it][half * 2 + 0] + __ldg(P.b0 + col0)     + __ldg(P.b1 + col0);
                float v1 = c[im][it][half * 2 + 1] + __ldg(P.b0 + col0 + 1) + __ldg(P.b1 + col0 + 1);
                float z0 = P.z[idx], z1 = P.z[idx + 1];
                float h0 = z0 * P.h[idx]     + (1.f - z0) * tanhf(v0);
                float h1 = z1 * P.h[idx + 1] + (1.f - z1) * tanhf(v1);
                P.out[idx] = h0;
                P.out[idx + 1] = h1;
                *(__half2*)(P.out16 + idx) = __floats2half2_rn(h0, h1);
            }
        }
    }
}

// ---------------- output projection (+ state reset on final step) ----------------
__global__ void k_proj(const float* __restrict__ h, __half* __restrict__ h16,
                       const float* __restrict__ Wl, const float* __restrict__ bl,
                       float* __restrict__ out, int zero_h) {
    int n = blockIdx.x * 8 + (threadIdx.x >> 5);
    if (n >= N_) return;
    int lane = threadIdx.x & 31;
    float4 a = *(const float4*)(h + n * H_ + lane * 4);
    float4 w = *(const float4*)(Wl + lane * 4);
    float s = a.x * w.x + a.y * w.y + a.z * w.z + a.w * w.w;
#pragma unroll
    for (int o = 16; o; o >>= 1) s += __shfl_down_sync(0xffffffffu, s, o);
    if (lane == 0) out[n] = s + bl[0];
    if (zero_h) {   // restore h=0 (fp32 + fp16) for the next replay
        *(float4*)((float*)h + n * H_ + lane * 4) = make_float4(0.f, 0.f, 0.f, 0.f);
        ((uint2*)h16)[n * 32 + lane] = make_uint2(0u, 0u);
    }
}

// ---------------- driver ----------------
extern "C" void kernel_launch(void* const* d_in, const int* in_sizes, int n_in,
                              void* d_out, int out_size) {
    const float* x_seq = (const float*)d_in[0];
    const void*  ei    = d_in[1];
    const float* Wxz = (const float*)d_in[2];  const float* bxz = (const float*)d_in[3];
    const float* Whz = (const float*)d_in[4];  const float* bhz = (const float*)d_in[5];
    const float* Wxr = (const float*)d_in[6];  const float* bxr = (const float*)d_in[7];
    const float* Whr = (const float*)d_in[8];  const float* bhr = (const float*)d_in[9];
    const float* Wxh = (const float*)d_in[10]; const float* bxh = (const float*)d_in[11];
    const float* Whh = (const float*)d_in[12]; const float* bhh = (const float*)d_in[13];
    const float* Wl  = (const float*)d_in[14]; const float* bl  = (const float*)d_in[15];
    float* out = (float*)d_out;

    float *TxB1, *Th1, *Ts1, *h, *z, *s;
    __half *x16, *TxB1h, *TxB2h, *Th1h, *Th2h, *Ts1h, *Ts2h, *h16, *s16, *Wt;
    cudaGetSymbolAddress((void**)&TxB1,  g_TxB1);
    cudaGetSymbolAddress((void**)&x16,   g_x16);
    cudaGetSymbolAddress((void**)&TxB1h, g_TxB1h);
    cudaGetSymbolAddress((void**)&TxB2h, g_TxB2h);
    cudaGetSymbolAddress((void**)&Th1,   g_Th1);
    cudaGetSymbolAddress((void**)&Th1h,  g_Th1h);
    cudaGetSymbolAddress((void**)&Th2h,  g_Th2h);
    cudaGetSymbolAddress((void**)&Ts1,   g_Ts1);
    cudaGetSymbolAddress((void**)&Ts1h,  g_Ts1h);
    cudaGetSymbolAddress((void**)&Ts2h,  g_Ts2h);
    cudaGetSymbolAddress((void**)&h,     g_h);
    cudaGetSymbolAddress((void**)&h16,   g_h16);
    cudaGetSymbolAddress((void**)&z,     g_z);
    cudaGetSymbolAddress((void**)&s,     g_s);
    cudaGetSymbolAddress((void**)&s16,   g_s16);
    cudaGetSymbolAddress((void**)&Wt,    g_Wt);

    // preprocessing: 3 launches (profiled 4th launch = hot batched prop)
    W6 w6; w6.p[0] = Wxz; w6.p[1] = Whz; w6.p[2] = Wxr; w6.p[3] = Whr; w6.p[4] = Wxh; w6.p[5] = Whh;
    k_count<<<(E_ + 255) / 256, 256>>>(ei, x_seq, w6);
    k_scan <<<1, 1024>>>();
    k_fill <<<(E_ + 255) / 256, 256>>>(ei);

    const int WK = F_ * H_;               // 16384 halves per weight slice
    const int GB = (N_ + 63) / 64;        // 157
    const int PB = N_ / 8;                // 1250

    // ---- batched x-chain props: hop1 dual-write, hop2 fp16-only ----
    k_propv<<<dim3(PB, T_), 256>>>(x_seq, TxB1, TxB1h, nullptr, 1.f, 1);
    k_propv<<<dim3(PB, T_), 256>>>(TxB1, nullptr, TxB2h, x_seq, 2.f, 0);

    // ---- recurrence ----
    for (int t = 0; t < T_; t++) {
        const __half* xt16  = x16   + (size_t)t * NH;
        const __half* tx1h  = TxB1h + (size_t)t * NH;
        const __half* tx2h  = TxB2h + (size_t)t * NH;

        k_propv<<<dim3(PB, 1), 256>>>(h,   Th1, Th1h, nullptr, 1.f, 0);
        k_propv<<<dim3(PB, 1), 256>>>(Th1, nullptr, Th2h, h,   2.f, 0);

        GZR zr;
        zr.A[0] = xt16; zr.A[1] = tx1h; zr.A[2] = tx2h;
        zr.A[3] = h16;  zr.A[4] = Th1h; zr.A[5] = Th2h;
        for (int k = 0; k < 3; k++) {
            zr.Bz[k] = Wt + (0 * 3 + k) * WK; zr.Bz[3 + k] = Wt + (1 * 3 + k) * WK;
            zr.Br[k] = Wt + (2 * 3 + k) * WK; zr.Br[3 + k] = Wt + (3 * 3 + k) * WK;
        }
        zr.bz0 = bxz; zr.bz1 = bhz; zr.br0 = bxr; zr.br1 = bhr;
        zr.h = h; zr.zout = z; zr.sout = s; zr.sout16 = s16;
        k_gemm_zr<<<dim3(GB, 2), 128>>>(zr);

        k_propv<<<dim3(PB, 1), 256>>>(s,   Ts1, Ts1h, nullptr, 1.f, 0);
        k_propv<<<dim3(PB, 1), 256>>>(Ts1, nullptr, Ts2h, s,   2.f, 0);

        GH gh;
        gh.A[0] = xt16; gh.A[1] = tx1h; gh.A[2] = tx2h;
        gh.A[3] = s16;  gh.A[4] = Ts1h; gh.A[5] = Ts2h;
        for (int k = 0; k < 3; k++) {
            gh.B[k] = Wt + (4 * 3 + k) * WK; gh.B[3 + k] = Wt + (5 * 3 + k) * WK;
        }
        gh.b0 = bxh; gh.b1 = bhh; gh.h = h; gh.z = z; gh.out = h; gh.out16 = h16;
        k_gemm_h<<<dim3(GB, 2), 128>>>(gh);

        k_proj<<<(N_ + 7) / 8, 256>>>(h, h16, Wl, bl, out + t * N_, t == T_ - 1);
    }
    (void)in_sizes; (void)n_in; (void)out_size;
}

// round 9
// speedup vs baseline: 1.5432x; 1.0666x over previous
#include <cuda_runtime.h>
#include <cuda_fp16.h>
#include <cstdint>

#define T_ 12
#define N_ 10000
#define F_ 128
#define H_ 128
#define E_ 320000
#define NH (N_*H_)
#define TNH (T_*NH)
#define WSLICE (3*F_*H_)

// ---------------- scratch (static device memory) ----------------
__device__ __align__(16) float  g_TxB1[TNH];
__device__ __align__(16) __half g_x16 [TNH];
__device__ __align__(16) __half g_TxB1h[TNH];
__device__ __align__(16) __half g_TxB2h[TNH];
__device__ __align__(16) float  g_Th1[NH];
__device__ __align__(16) __half g_Th1h[NH];
__device__ __align__(16) __half g_Th2h[NH];
__device__ __align__(16) float  g_Ts1[NH];
__device__ __align__(16) __half g_Ts1h[NH];
__device__ __align__(16) __half g_Ts2h[NH];
__device__ __align__(16) float  g_h  [NH];
__device__ __align__(16) __half g_h16[NH];
__device__ __align__(16) float  g_z  [NH];
__device__ __align__(16) float  g_s  [NH];
__device__ __align__(16) __half g_s16[NH];
__device__ __align__(16) __half g_Wt [6 * WSLICE];
__device__ float g_deg[N_];
__device__ int   g_cnt[N_];
__device__ int   g_rowptr[N_ + 1];
__device__ int   g_wr[N_];
__device__ __align__(16) int2 g_cv[E_];   // {src*32, val bits}

__device__ __forceinline__ bool probe_is64(const void* ei) {
    const int* p = (const int*)ei;
    int acc = 0;
#pragma unroll
    for (int i = 1; i < 32; i += 2) acc |= p[i];
    return acc == 0;
}
__device__ __forceinline__ int edge_at(const void* ei, int idx, bool is64) {
    if (is64) return (int)((const long long*)ei)[idx];
    return ((const int*)ei)[idx];
}

// ---------------- preprocessing (3 launches) ----------------
struct W6 { const float* p[6]; };
__global__ void k_count(const void* __restrict__ ei, const float* __restrict__ x_seq, W6 w) {
    int e = blockIdx.x * blockDim.x + threadIdx.x;
    if (e < 6 * WSLICE) {                       // W[k][n] -> Wt[n][k] fp16
        int which = e / WSLICE;
        int r = e - which * WSLICE;
        int slice = r / (F_ * H_);
        int r2 = r - slice * (F_ * H_);
        int n = r2 >> 7, k = r2 & 127;
        g_Wt[e] = __float2half(w.p[which][slice * F_ * H_ + k * H_ + n]);
    }
    const float4* x4 = (const float4*)x_seq;    // x_seq -> fp16 shadow
    uint2* o16 = (uint2*)g_x16;
    for (int i = e; i < TNH / 4; i += 320000) {
        float4 v = x4[i];
        __half2 p0 = __floats2half2_rn(v.x, v.y);
        __half2 p1 = __floats2half2_rn(v.z, v.w);
        uint2 u; u.x = *(uint32_t*)&p0; u.y = *(uint32_t*)&p1;
        o16[i] = u;
    }
    if (e >= E_) return;
    bool is64 = probe_is64(ei);
    int s = edge_at(ei, e, is64);
    int d = edge_at(ei, E_ + e, is64);
    if ((unsigned)s >= N_ || (unsigned)d >= N_) return;
    atomicAdd(&g_deg[s], 1.0f);
    atomicAdd(&g_cnt[d], 1);
}

__global__ void k_scan() {
    __shared__ int sh[1024];
    int tid = threadIdx.x;
    for (int i = tid; i < N_; i += 1024) {
        float d = g_deg[i];
        g_deg[i] = (d > 0.f) ? rsqrtf(d) : 0.f;
    }
    const int PER = (N_ + 1023) / 1024;
    int base = tid * PER;
    int s = 0;
    for (int i = 0; i < PER; i++) { int ix = base + i; if (ix < N_) s += g_cnt[ix]; }
    sh[tid] = s;
    __syncthreads();
    for (int off = 1; off < 1024; off <<= 1) {
        int v = (tid >= off) ? sh[tid - off] : 0;
        __syncthreads();
        if (tid >= off) sh[tid] += v;
        __syncthreads();
    }
    int run = (tid > 0) ? sh[tid - 1] : 0;
    for (int i = 0; i < PER; i++) {
        int ix = base + i;
        if (ix < N_) { g_rowptr[ix] = run; g_wr[ix] = run; run += g_cnt[ix]; }
    }
    if (tid == 0) g_rowptr[N_] = sh[1023];
}

__global__ void k_fill(const void* __restrict__ ei) {
    int e = blockIdx.x * blockDim.x + threadIdx.x;
    if (e >= E_) return;
    bool is64 = probe_is64(ei);
    int s = edge_at(ei, e, is64);
    int d = edge_at(ei, E_ + e, is64);
    if ((unsigned)s >= N_ || (unsigned)d >= N_) return;
    int slot = atomicAdd(&g_wr[d], 1);
    float v = -g_deg[s] * g_deg[d];
    g_cv[slot] = make_int2(s * 32, __float_as_int(v));
}

// ---------------- vectorized propagation (unroll-4, optional fused proj) ----------------
// out[t,n,:] = scale*sum val*in[t,col,:] - sub[t,n,:]; out fp32 nullable, out16 always.
// If projout != null (hop1-on-h launches): projout[n] = dot(in[n,:], Wl) + bl.
__global__ __launch_bounds__(256) void k_propv(const float* __restrict__ in,
                                               float* __restrict__ out,
                                               __half* __restrict__ out16,
                                               const float* __restrict__ sub,
                                               float scale, int clear,
                                               const float* __restrict__ Wl,
                                               const float* __restrict__ bl,
                                               float* __restrict__ projout) {
    const int lane = threadIdx.x & 31;
    const int n = blockIdx.x * 8 + (threadIdx.x >> 5);
    const int t = blockIdx.y;
    if (clear && t == 0 && lane == 0) { g_cnt[n] = 0; g_deg[n] = 0.f; }
    const size_t off4 = (size_t)t * (NH / 4);
    const float4* in4 = (const float4*)in + off4;
    int e = g_rowptr[n];
    const int end = g_rowptr[n + 1];

    float4 a0 = make_float4(0.f, 0.f, 0.f, 0.f);
    float4 a1 = make_float4(0.f, 0.f, 0.f, 0.f);
    float4 a2 = make_float4(0.f, 0.f, 0.f, 0.f);
    float4 a3 = make_float4(0.f, 0.f, 0.f, 0.f);

    if ((e & 1) && e < end) {                    // peel to even e for int4 cv loads
        int2 cv = g_cv[e];
        float w = __int_as_float(cv.y);
        float4 v = __ldg(in4 + cv.x + lane);
        a0.x += w * v.x; a0.y += w * v.y; a0.z += w * v.z; a0.w += w * v.w;
        e++;
    }
#pragma unroll 1
    for (; e + 4 <= end; e += 4) {
        int4 c01 = *(const int4*)(g_cv + e);
        int4 c23 = *(const int4*)(g_cv + e + 2);
        float w0 = __int_as_float(c01.y), w1 = __int_as_float(c01.w);
        float w2 = __int_as_float(c23.y), w3 = __int_as_float(c23.w);
        float4 v0 = __ldg(in4 + c01.x + lane);
        float4 v1 = __ldg(in4 + c01.z + lane);
        float4 v2 = __ldg(in4 + c23.x + lane);
        float4 v3 = __ldg(in4 + c23.z + lane);
        a0.x += w0 * v0.x; a0.y += w0 * v0.y; a0.z += w0 * v0.z; a0.w += w0 * v0.w;
        a1.x += w1 * v1.x; a1.y += w1 * v1.y; a1.z += w1 * v1.z; a1.w += w1 * v1.w;
        a2.x += w2 * v2.x; a2.y += w2 * v2.y; a2.z += w2 * v2.z; a2.w += w2 * v2.w;
        a3.x += w3 * v3.x; a3.y += w3 * v3.y; a3.z += w3 * v3.z; a3.w += w3 * v3.w;
    }
#pragma unroll 1
    for (; e < end; e++) {
        int2 cv = g_cv[e];
        float w = __int_as_float(cv.y);
        float4 v = __ldg(in4 + cv.x + lane);
        a0.x += w * v.x; a0.y += w * v.y; a0.z += w * v.z; a0.w += w * v.w;
    }
    float4 r;
    r.x = scale * ((a0.x + a1.x) + (a2.x + a3.x));
    r.y = scale * ((a0.y + a1.y) + (a2.y + a3.y));
    r.z = scale * ((a0.z + a1.z) + (a2.z + a3.z));
    r.w = scale * ((a0.w + a1.w) + (a2.w + a3.w));
    const int oidx = n * 32 + lane;
    if (sub) {
        float4 sb = __ldg((const float4*)sub + off4 + oidx);
        r.x -= sb.x; r.y -= sb.y; r.z -= sb.z; r.w -= sb.w;
    }
    if (out) ((float4*)out + off4)[oidx] = r;
    __half2 p0 = __floats2half2_rn(r.x, r.y);
    __half2 p1 = __floats2half2_rn(r.z, r.w);
    uint2 u; u.x = *(uint32_t*)&p0; u.y = *(uint32_t*)&p1;
    ((uint2*)out16 + off4)[oidx] = u;

    if (projout) {                               // fused proj of previous step (in == h)
        float4 hv = __ldg(in4 + n * 32 + lane);
        float4 wv = __ldg((const float4*)Wl + lane);
        float d = hv.x * wv.x + hv.y * wv.y + hv.z * wv.z + hv.w * wv.w;
#pragma unroll
        for (int o = 16; o; o >>= 1) d += __shfl_down_sync(0xffffffffu, d, o);
        if (lane == 0) projout[n] = d + __ldg(bl);
    }
}

// ---------------- fp16 tensor-core GEMMs (m16n8k16, fp32 accum) ----------------
__device__ __forceinline__ float sigf(float x) { return 1.f / (1.f + expf(-x)); }
__device__ __forceinline__ void cp16(uint32_t dst, const void* src) {
    asm volatile("cp.async.cg.shared.global [%0], [%1], 16;\n" :: "r"(dst), "l"(src));
}
__device__ __forceinline__ void mma_f16(float c[4], const uint32_t a[4], const uint32_t b[2]) {
    asm volatile(
        "mma.sync.aligned.m16n8k16.row.col.f32.f16.f16.f32 "
        "{%0,%1,%2,%3}, {%4,%5,%6,%7}, {%8,%9}, {%0,%1,%2,%3};\n"
        : "+f"(c[0]), "+f"(c[1]), "+f"(c[2]), "+f"(c[3])
        : "r"(a[0]), "r"(a[1]), "r"(a[2]), "r"(a[3]), "r"(b[0]), "r"(b[1]));
}

#define HS 40
#define TILE_H (64 * HS)

// ---- fused z + r GEMM (npairs pairs; t0 path writes z only) ----
struct GZR {
    const __half* A[6];
    const __half* Bz[6];
    const __half* Br[6];
    const float* bz0; const float* bz1;
    const float* br0; const float* br1;
    const float* h;
    float* zout; float* sout; __half* sout16;   // sout == null => t0 (skip s)
    int npairs;
};

__global__ __launch_bounds__(128) void k_gemm_zr(GZR P) {
    __shared__ __half As[2][TILE_H], Bzs[2][TILE_H], Brs[2][TILE_H];

    const int tid  = threadIdx.x;
    const int wid  = tid >> 5, lane = tid & 31;
    const int g    = lane >> 2, tig = lane & 3;
    const int wm   = wid >> 1, wn = wid & 1;
    const int bm   = blockIdx.x * 64;
    const int bn   = blockIdx.y * 64;
    const int nst  = P.npairs * 4;

    float cz[2][4][4], cr[2][4][4];
#pragma unroll
    for (int im = 0; im < 2; im++)
#pragma unroll
        for (int it = 0; it < 4; it++)
#pragma unroll
            for (int q = 0; q < 4; q++) { cz[im][it][q] = 0.f; cr[im][it][q] = 0.f; }

    auto issue = [&](int s) {
        int pr = s >> 2, ch = s & 3, buf = s & 1;
        uint32_t sA = (uint32_t)__cvta_generic_to_shared(&As[buf][0]);
        uint32_t sZ = (uint32_t)__cvta_generic_to_shared(&Bzs[buf][0]);
        uint32_t sR = (uint32_t)__cvta_generic_to_shared(&Brs[buf][0]);
        const __half* Ap = P.A[pr];
        const __half* Zp = P.Bz[pr];
        const __half* Rp = P.Br[pr];
#pragma unroll
        for (int i = 0; i < 2; i++) {
            int fi = tid + 128 * i;
            int row = fi >> 2, c8 = fi & 3;
            int ar = bm + row; if (ar > N_ - 1) ar = N_ - 1;
            uint32_t so = (uint32_t)(row * HS + c8 * 8) * 2;
            cp16(sA + so, Ap + (size_t)ar * H_ + ch * 32 + c8 * 8);
            cp16(sZ + so, Zp + (bn + row) * H_ + ch * 32 + c8 * 8);
            cp16(sR + so, Rp + (bn + row) * H_ + ch * 32 + c8 * 8);
        }
        asm volatile("cp.async.commit_group;\n" ::: "memory");
    };

    issue(0);
#pragma unroll 1
    for (int s = 0; s < nst; s++) {
        if (s + 1 < nst) {
            issue(s + 1);
            asm volatile("cp.async.wait_group 1;\n" ::: "memory");
        } else {
            asm volatile("cp.async.wait_group 0;\n" ::: "memory");
        }
        __syncthreads();
        const __half* As_ = As[s & 1];
        const __half* Bz_ = Bzs[s & 1];
        const __half* Br_ = Brs[s & 1];
#pragma unroll
        for (int ks = 0; ks < 2; ks++) {
            const int k0 = ks * 16;
            uint32_t a[2][4];
#pragma unroll
            for (int im = 0; im < 2; im++) {
                int r0 = wm * 32 + im * 16 + g;
                a[im][0] = *(const uint32_t*)(As_ + r0 * HS + k0 + 2 * tig);
                a[im][1] = *(const uint32_t*)(As_ + (r0 + 8) * HS + k0 + 2 * tig);
                a[im][2] = *(const uint32_t*)(As_ + r0 * HS + k0 + 2 * tig + 8);
                a[im][3] = *(const uint32_t*)(As_ + (r0 + 8) * HS + k0 + 2 * tig + 8);
            }
            uint32_t bz[4][2], br[4][2];
#pragma unroll
            for (int it = 0; it < 4; it++) {
                int cb = wn * 32 + it * 8 + g;
                bz[it][0] = *(const uint32_t*)(Bz_ + cb * HS + k0 + 2 * tig);
                bz[it][1] = *(const uint32_t*)(Bz_ + cb * HS + k0 + 2 * tig + 8);
                br[it][0] = *(const uint32_t*)(Br_ + cb * HS + k0 + 2 * tig);
                br[it][1] = *(const uint32_t*)(Br_ + cb * HS + k0 + 2 * tig + 8);
            }
#pragma unroll
            for (int im = 0; im < 2; im++)
#pragma unroll
                for (int it = 0; it < 4; it++) {
                    mma_f16(cz[im][it], a[im], bz[it]);
                    mma_f16(cr[im][it], a[im], br[it]);
                }
        }
        __syncthreads();
    }

#pragma unroll
    for (int im = 0; im < 2; im++) {
        int rbase = bm + wm * 32 + im * 16 + g;
#pragma unroll
        for (int half = 0; half < 2; half++) {
            int row = rbase + half * 8;
            if (row >= N_) continue;
#pragma unroll
            for (int it = 0; it < 4; it++) {
                int col0 = bn + wn * 32 + it * 8 + 2 * tig;
                int idx = row * H_ + col0;
                float vz0 = cz[im][it][half * 2 + 0] + __ldg(P.bz0 + col0)     + __ldg(P.bz1 + col0);
                float vz1 = cz[im][it][half * 2 + 1] + __ldg(P.bz0 + col0 + 1) + __ldg(P.bz1 + col0 + 1);
                P.zout[idx] = sigf(vz0);
                P.zout[idx + 1] = sigf(vz1);
                if (P.sout) {
                    float vr0 = cr[im][it][half * 2 + 0] + __ldg(P.br0 + col0)     + __ldg(P.br1 + col0);
                    float vr1 = cr[im][it][half * 2 + 1] + __ldg(P.br0 + col0 + 1) + __ldg(P.br1 + col0 + 1);
                    float s0 = P.h[idx] * sigf(vr0);
                    float s1 = P.h[idx + 1] * sigf(vr1);
                    P.sout[idx] = s0;
                    P.sout[idx + 1] = s1;
                    *(__half2*)(P.sout16 + idx) = __floats2half2_rn(s0, s1);
                }
            }
        }
    }
}

// ---- h-update GEMM: h = z*h + (1-z)*tanh(acc + b0 + b1); h==null => old state 0 ----
struct GH {
    const __half* A[6];
    const __half* B[6];
    const float* b0; const float* b1;
    const float* h;  const float* z;
    float* out; __half* out16;
    int npairs;
};

__global__ __launch_bounds__(128) void k_gemm_h(GH P) {
    __shared__ __half As[2][TILE_H], Bs[2][TILE_H];

    const int tid  = threadIdx.x;
    const int wid  = tid >> 5, lane = tid & 31;
    const int g    = lane >> 2, tig = lane & 3;
    const int wm   = wid >> 1, wn = wid & 1;
    const int bm   = blockIdx.x * 64;
    const int bn   = blockIdx.y * 64;
    const int nst  = P.npairs * 4;

    float c[2][4][4];
#pragma unroll
    for (int im = 0; im < 2; im++)
#pragma unroll
        for (int it = 0; it < 4; it++)
#pragma unroll
            for (int q = 0; q < 4; q++) c[im][it][q] = 0.f;

    auto issue = [&](int s) {
        int pr = s >> 2, ch = s & 3, buf = s & 1;
        uint32_t sA = (uint32_t)__cvta_generic_to_shared(&As[buf][0]);
        uint32_t sB = (uint32_t)__cvta_generic_to_shared(&Bs[buf][0]);
        const __half* Ap = P.A[pr];
        const __half* Bp = P.B[pr];
#pragma unroll
        for (int i = 0; i < 2; i++) {
            int fi = tid + 128 * i;
            int row = fi >> 2, c8 = fi & 3;
            int ar = bm + row; if (ar > N_ - 1) ar = N_ - 1;
            uint32_t so = (uint32_t)(row * HS + c8 * 8) * 2;
            cp16(sA + so, Ap + (size_t)ar * H_ + ch * 32 + c8 * 8);
            cp16(sB + so, Bp + (bn + row) * H_ + ch * 32 + c8 * 8);
        }
        asm volatile("cp.async.commit_group;\n" ::: "memory");
    };

    issue(0);
#pragma unroll 1
    for (int s = 0; s < nst; s++) {
        if (s + 1 < nst) {
            issue(s + 1);
            asm volatile("cp.async.wait_group 1;\n" ::: "memory");
        } else {
            asm volatile("cp.async.wait_group 0;\n" ::: "memory");
        }
        __syncthreads();
        const __half* As_ = As[s & 1];
        const __half* Bs_ = Bs[s & 1];
#pragma unroll
        for (int ks = 0; ks < 2; ks++) {
            const int k0 = ks * 16;
            uint32_t a[2][4];
#pragma unroll
            for (int im = 0; im < 2; im++) {
                int r0 = wm * 32 + im * 16 + g;
                a[im][0] = *(const uint32_t*)(As_ + r0 * HS + k0 + 2 * tig);
                a[im][1] = *(const uint32_t*)(As_ + (r0 + 8) * HS + k0 + 2 * tig);
                a[im][2] = *(const uint32_t*)(As_ + r0 * HS + k0 + 2 * tig + 8);
                a[im][3] = *(const uint32_t*)(As_ + (r0 + 8) * HS + k0 + 2 * tig + 8);
            }
            uint32_t b[4][2];
#pragma unroll
            for (int it = 0; it < 4; it++) {
                int cb = wn * 32 + it * 8 + g;
                b[it][0] = *(const uint32_t*)(Bs_ + cb * HS + k0 + 2 * tig);
                b[it][1] = *(const uint32_t*)(Bs_ + cb * HS + k0 + 2 * tig + 8);
            }
#pragma unroll
            for (int im = 0; im < 2; im++)
#pragma unroll
                for (int it = 0; it < 4; it++) mma_f16(c[im][it], a[im], b[it]);
        }
        __syncthreads();
    }

#pragma unroll
    for (int im = 0; im < 2; im++) {
        int rbase = bm + wm * 32 + im * 16 + g;
#pragma unroll
        for (int half = 0; half < 2; half++) {
            int row = rbase + half * 8;
            if (row >= N_) continue;
#pragma unroll
            for (int it = 0; it < 4; it++) {
                int col0 = bn + wn * 32 + it * 8 + 2 * tig;
                int idx = row * H_ + col0;
                float v0 = c[im][it][half * 2 + 0] + __ldg(P.b0 + col0)     + __ldg(P.b1 + col0);
                float v1 = c[im][it][half * 2 + 1] + __ldg(P.b0 + col0 + 1) + __ldg(P.b1 + col0 + 1);
                float z0 = P.z[idx], z1 = P.z[idx + 1];
                float h00 = P.h ? P.h[idx]     : 0.f;
                float h01 = P.h ? P.h[idx + 1] : 0.f;
                float h0 = z0 * h00 + (1.f - z0) * tanhf(v0);
                float h1 = z1 * h01 + (1.f - z1) * tanhf(v1);
                P.out[idx] = h0;
                P.out[idx + 1] = h1;
                *(__half2*)(P.out16 + idx) = __floats2half2_rn(h0, h1);
            }
        }
    }
}

// ---------------- standalone projection (final step only) ----------------
__global__ void k_proj(const float* __restrict__ h, const float* __restrict__ Wl,
                       const float* __restrict__ bl, float* __restrict__ out) {
    int n = blockIdx.x * 8 + (threadIdx.x >> 5);
    if (n >= N_) return;
    int lane = threadIdx.x & 31;
    float4 a = *(const float4*)(h + n * H_ + lane * 4);
    float4 w = *(const float4*)(Wl + lane * 4);
    float s = a.x * w.x + a.y * w.y + a.z * w.z + a.w * w.w;
#pragma unroll
    for (int o = 16; o; o >>= 1) s += __shfl_down_sync(0xffffffffu, s, o);
    if (lane == 0) out[n] = s + bl[0];
}

// ---------------- driver ----------------
extern "C" void kernel_launch(void* const* d_in, const int* in_sizes, int n_in,
                              void* d_out, int out_size) {
    const float* x_seq = (const float*)d_in[0];
    const void*  ei    = d_in[1];
    const float* Wxz = (const float*)d_in[2];  const float* bxz = (const float*)d_in[3];
    const float* Whz = (const float*)d_in[4];  const float* bhz = (const float*)d_in[5];
    const float* Wxr = (const float*)d_in[6];  const float* bxr = (const float*)d_in[7];
    const float* Whr = (const float*)d_in[8];  const float* bhr = (const float*)d_in[9];
    const float* Wxh = (const float*)d_in[10]; const float* bxh = (const float*)d_in[11];
    const float* Whh = (const float*)d_in[12]; const float* bhh = (const float*)d_in[13];
    const float* Wl  = (const float*)d_in[14]; const float* bl  = (const float*)d_in[15];
    float* out = (float*)d_out;

    float *TxB1, *Th1, *Ts1, *h, *z, *s;
    __half *x16, *TxB1h, *TxB2h, *Th1h, *Th2h, *Ts1h, *Ts2h, *h16, *s16, *Wt;
    cudaGetSymbolAddress((void**)&TxB1,  g_TxB1);
    cudaGetSymbolAddress((void**)&x16,   g_x16);
    cudaGetSymbolAddress((void**)&TxB1h, g_TxB1h);
    cudaGetSymbolAddress((void**)&TxB2h, g_TxB2h);
    cudaGetSymbolAddress((void**)&Th1,   g_Th1);
    cudaGetSymbolAddress((void**)&Th1h,  g_Th1h);
    cudaGetSymbolAddress((void**)&Th2h,  g_Th2h);
    cudaGetSymbolAddress((void**)&Ts1,   g_Ts1);
    cudaGetSymbolAddress((void**)&Ts1h,  g_Ts1h);
    cudaGetSymbolAddress((void**)&Ts2h,  g_Ts2h);
    cudaGetSymbolAddress((void**)&h,     g_h);
    cudaGetSymbolAddress((void**)&h16,   g_h16);
    cudaGetSymbolAddress((void**)&z,     g_z);
    cudaGetSymbolAddress((void**)&s,     g_s);
    cudaGetSymbolAddress((void**)&s16,   g_s16);
    cudaGetSymbolAddress((void**)&Wt,    g_Wt);

    // preprocessing: 3 launches (profiled 4th launch = hot batched prop)
    W6 w6; w6.p[0] = Wxz; w6.p[1] = Whz; w6.p[2] = Wxr; w6.p[3] = Whr; w6.p[4] = Wxh; w6.p[5] = Whh;
    k_count<<<(E_ + 255) / 256, 256>>>(ei, x_seq, w6);
    k_scan <<<1, 1024>>>();
    k_fill <<<(E_ + 255) / 256, 256>>>(ei);

    const int WK = F_ * H_;
    const int GB = (N_ + 63) / 64;
    const int PB = N_ / 8;

    // ---- batched x-chain props ----
    k_propv<<<dim3(PB, T_), 256>>>(x_seq, TxB1, TxB1h, nullptr, 1.f, 1, nullptr, nullptr, nullptr);
    k_propv<<<dim3(PB, T_), 256>>>(TxB1, nullptr, TxB2h, x_seq, 2.f, 0, nullptr, nullptr, nullptr);

    // ---- recurrence ----
    for (int t = 0; t < T_; t++) {
        const __half* xt16 = x16   + (size_t)t * NH;
        const __half* tx1h = TxB1h + (size_t)t * NH;
        const __half* tx2h = TxB2h + (size_t)t * NH;
        const bool t0 = (t == 0);

        if (!t0) {
            // hop1 on h also emits proj output of step t-1 (h is post-step-(t-1) state)
            k_propv<<<dim3(PB, 1), 256>>>(h, Th1, Th1h, nullptr, 1.f, 0,
                                          Wl, bl, out + (size_t)(t - 1) * N_);
            k_propv<<<dim3(PB, 1), 256>>>(Th1, nullptr, Th2h, h, 2.f, 0,
                                          nullptr, nullptr, nullptr);
        }

        GZR zr;
        zr.A[0] = xt16; zr.A[1] = tx1h; zr.A[2] = tx2h;
        zr.A[3] = h16;  zr.A[4] = Th1h; zr.A[5] = Th2h;
        for (int k = 0; k < 3; k++) {
            zr.Bz[k] = Wt + (0 * 3 + k) * WK; zr.Bz[3 + k] = Wt + (1 * 3 + k) * WK;
            zr.Br[k] = Wt + (2 * 3 + k) * WK; zr.Br[3 + k] = Wt + (3 * 3 + k) * WK;
        }
        zr.bz0 = bxz; zr.bz1 = bhz; zr.br0 = bxr; zr.br1 = bhr;
        zr.h = h; zr.zout = z;
        zr.sout = t0 ? nullptr : s; zr.sout16 = s16;
        zr.npairs = t0 ? 3 : 6;
        k_gemm_zr<<<dim3(GB, 2), 128>>>(zr);

        if (!t0) {
            k_propv<<<dim3(PB, 1), 256>>>(s, Ts1, Ts1h, nullptr, 1.f, 0,
                                          nullptr, nullptr, nullptr);
            k_propv<<<dim3(PB, 1), 256>>>(Ts1, nullptr, Ts2h, s, 2.f, 0,
                                          nullptr, nullptr, nullptr);
        }

        GH gh;
        gh.A[0] = xt16; gh.A[1] = tx1h; gh.A[2] = tx2h;
        gh.A[3] = s16;  gh.A[4] = Ts1h; gh.A[5] = Ts2h;
        for (int k = 0; k < 3; k++) {
            gh.B[k] = Wt + (4 * 3 + k) * WK; gh.B[3 + k] = Wt + (5 * 3 + k) * WK;
        }
        gh.b0 = bxh; gh.b1 = bhh;
        gh.h = t0 ? nullptr : h;
        gh.z = z; gh.out = h; gh.out16 = h16;
        gh.npairs = t0 ? 3 : 6;
        k_gemm_h<<<dim3(GB, 2), 128>>>(gh);
    }
    // final step's projection
    k_proj<<<(N_ + 7) / 8, 256>>>(h, Wl, bl, out + (size_t)(T_ - 1) * N_);

    (void)in_sizes; (void)n_in; (void)out_size;
}